// round 1
// baseline (speedup 1.0000x reference)
#include <cuda_runtime.h>
#include <cuda_bf16.h>

#define BSZ     4
#define D_MODEL 1024
#define QLEN    512
#define MLEN    512
#define KLEN    1024
#define NHEAD   16
#define DHEAD   64
#define DINNER  4096
#define LOCALSZ 256

// ---------------- scratch (device globals; no allocations allowed) ----------
__device__ float g_cat[BSZ * D_MODEL * KLEN];              // 16 MB
__device__ float g_wheads[BSZ * 3 * D_MODEL * KLEN];       // 48 MB
__device__ float g_rk[D_MODEL * KLEN];                     // 4 MB
__device__ float g_attnvec[BSZ * D_MODEL * QLEN];          // 8 MB
__device__ float g_tmp1[BSZ * D_MODEL * QLEN];             // 8 MB
__device__ float g_x[BSZ * D_MODEL * QLEN];                // 8 MB
__device__ float g_h[BSZ * DINNER * QLEN];                 // 32 MB
__device__ float g_tmp2[BSZ * D_MODEL * QLEN];             // 8 MB

// ---------------- concat [z0 | z1ss] along time ------------------------------
__global__ void cat_kernel(const float* __restrict__ z0,
                           const float* __restrict__ z1ss)
{
    long idx = (long)blockIdx.x * 256 + threadIdx.x;
    if (idx >= (long)BSZ * D_MODEL * KLEN) return;
    int  t  = (int)(idx & (KLEN - 1));
    long bd = idx >> 10;                 // b*D_MODEL + d
    if (t < MLEN) g_cat[idx] = z0[bd * MLEN + t];
    else          g_cat[idx] = z1ss[bd * QLEN + (t - MLEN)];
}

// ---------------- generic SGEMM: C = A(MxK) * B(KxN) [+bias][+addend][relu] --
// A row-major (shared across batch), B/C/addend batched row-major.
__global__ __launch_bounds__(256)
void gemm_kernel(const float* __restrict__ A,
                 const float* __restrict__ B,
                 float*       __restrict__ C,
                 const float* __restrict__ bias,
                 const float* __restrict__ addend,
                 int M, int N, int K,
                 long strideB, long strideC, long strideAdd,
                 int relu)
{
    const int BM = 128, BN = 64, BK = 16;
    __shared__ float As[BK][BM + 4];
    __shared__ float Bs[BK][BN];

    int tid = threadIdx.x;
    int bn  = blockIdx.x * BN;
    int bm  = blockIdx.y * BM;
    int bz  = blockIdx.z;
    const float* Bb = B + (long)bz * strideB;

    float acc[8][4];
#pragma unroll
    for (int r = 0; r < 8; r++)
#pragma unroll
        for (int c = 0; c < 4; c++) acc[r][c] = 0.f;

    int a_k = tid & 15;          // 0..15
    int a_m = tid >> 4;          // 0..15
    int b_n = tid & 63;          // 0..63
    int b_k = tid >> 6;          // 0..3
    int tx  = tid & 15;          // n sub-tile
    int ty  = tid >> 4;          // m sub-tile

    for (int k0 = 0; k0 < K; k0 += BK) {
#pragma unroll
        for (int i = 0; i < 8; i++) {
            int m = a_m + i * 16;
            As[a_k][m] = A[(long)(bm + m) * K + (k0 + a_k)];
        }
#pragma unroll
        for (int i = 0; i < 4; i++) {
            int k = b_k + i * 4;
            Bs[k][b_n] = Bb[(long)(k0 + k) * N + (bn + b_n)];
        }
        __syncthreads();
#pragma unroll
        for (int kk = 0; kk < BK; kk++) {
            float a[8], bb[4];
#pragma unroll
            for (int r = 0; r < 8; r++) a[r] = As[kk][ty * 8 + r];
#pragma unroll
            for (int c = 0; c < 4; c++) bb[c] = Bs[kk][tx * 4 + c];
#pragma unroll
            for (int r = 0; r < 8; r++)
#pragma unroll
                for (int c = 0; c < 4; c++)
                    acc[r][c] += a[r] * bb[c];
        }
        __syncthreads();
    }

    float* Cb = C + (long)bz * strideC;
    const float* Ad = addend ? (addend + (long)bz * strideAdd) : nullptr;
#pragma unroll
    for (int r = 0; r < 8; r++) {
        int m = bm + ty * 8 + r;
        float bv = bias ? bias[m] : 0.f;
#pragma unroll
        for (int c = 0; c < 4; c++) {
            int n = bn + tx * 4 + c;
            float v = acc[r][c] + bv;
            if (Ad)  v += Ad[(long)m * N + n];
            if (relu) v = fmaxf(v, 0.f);
            Cb[(long)m * N + n] = v;
        }
    }
}

// ---------------- banded attention ------------------------------------------
// Valid keys for query i: j in [i+257, i+512] (exactly 256).
// BD[i,j] = raw_bd[i, j-i+511]  ->  r_head_k column r = 768 + j' (i-independent).
__global__ __launch_bounds__(256)
void attn_kernel(const float* __restrict__ wheads,
                 const float* __restrict__ rk,
                 const float* __restrict__ rwb,
                 const float* __restrict__ rrb,
                 float*       __restrict__ avec)
{
    int i = blockIdx.x;          // query 0..511
    int h = blockIdx.y;          // head  0..15
    int b = blockIdx.z;          // batch 0..3
    int tid = threadIdx.x;       // 0..255

    __shared__ float qw[DHEAD], qr[DHEAD];
    __shared__ float sc[256];
    __shared__ float red[256];
    __shared__ float part[256];

    const float* W = wheads + (long)b * (3 * D_MODEL) * KLEN;

    if (tid < DHEAD) {
        float qv = W[(long)(h * DHEAD + tid) * KLEN + (MLEN + i)];
        qw[tid] = qv + rwb[h * DHEAD + tid];
        qr[tid] = qv + rrb[h * DHEAD + tid];
    }
    __syncthreads();

    // scores for j = i + 257 + tid
    {
        int j = i + 257 + tid;
        const float* Kp = W + (long)(D_MODEL + h * DHEAD) * KLEN + j;
        const float* Rp = rk + (long)(h * DHEAD) * KLEN + (768 + tid);
        float ac = 0.f, bd = 0.f;
#pragma unroll 8
        for (int d = 0; d < DHEAD; d++) {
            ac += qw[d] * Kp[(long)d * KLEN];
            bd += qr[d] * Rp[(long)d * KLEN];
        }
        float s = (ac + bd) * 0.125f;   // 1/sqrt(64)
        sc[tid] = s;
        red[tid] = s;
    }
    __syncthreads();
    for (int s = 128; s > 0; s >>= 1) {
        if (tid < s) red[tid] = fmaxf(red[tid], red[tid + s]);
        __syncthreads();
    }
    float mx = red[0];
    __syncthreads();
    float p = __expf(sc[tid] - mx);
    red[tid] = p;
    __syncthreads();
    for (int s = 128; s > 0; s >>= 1) {
        if (tid < s) red[tid] += red[tid + s];
        __syncthreads();
    }
    float inv = 1.0f / red[0];
    __syncthreads();
    sc[tid] = p * inv;
    __syncthreads();

    // attn_vec: sum_j prob[j'] * V[d, i+257+j']
    {
        int d  = tid & 63;
        int pg = tid >> 6;      // 0..3
        const float* Vp = W + (long)(2 * D_MODEL + h * DHEAD + d) * KLEN + (i + 257);
        float acc = 0.f;
        int j0 = pg * 64;
#pragma unroll 8
        for (int jj = 0; jj < 64; jj++)
            acc += sc[j0 + jj] * Vp[j0 + jj];
        part[tid] = acc;
    }
    __syncthreads();
    if (tid < DHEAD) {
        float v = part[tid] + part[64 + tid] + part[128 + tid] + part[192 + tid];
        avec[(long)b * D_MODEL * QLEN + (long)(h * DHEAD + tid) * QLEN + i] = v;
    }
}

// ---------------- channel LayerNorm (over axis=1, 1024 channels) -------------
__global__ __launch_bounds__(256)
void ln_kernel(const float* __restrict__ y, float* __restrict__ out)
{
    int b  = blockIdx.y;
    int t0 = blockIdx.x * 32;
    int tid = threadIdx.x;
    int tt = tid & 31, cg = tid >> 5;    // cg 0..7, each covers 128 channels
    const float* Y = y + (long)b * D_MODEL * QLEN;

    float s = 0.f, s2 = 0.f;
    for (int c = cg * 128; c < cg * 128 + 128; c++) {
        float v = Y[(long)c * QLEN + t0 + tt];
        s += v; s2 += v * v;
    }
    __shared__ float ssum[8][32], ssq[8][32];
    __shared__ float smean[32], srstd[32];
    ssum[cg][tt] = s; ssq[cg][tt] = s2;
    __syncthreads();
    if (tid < 32) {
        float ts = 0.f, ts2 = 0.f;
#pragma unroll
        for (int g = 0; g < 8; g++) { ts += ssum[g][tid]; ts2 += ssq[g][tid]; }
        float mean = ts * (1.0f / D_MODEL);
        float var  = ts2 * (1.0f / D_MODEL) - mean * mean;
        smean[tid] = mean;
        srstd[tid] = rsqrtf(var + 1e-5f);
    }
    __syncthreads();
    float mean = smean[tt], rstd = srstd[tt];
    float* O = out + (long)b * D_MODEL * QLEN;
    for (int c = cg * 128; c < cg * 128 + 128; c++) {
        float v = Y[(long)c * QLEN + t0 + tt];
        O[(long)c * QLEN + t0 + tt] = (v - mean) * rstd;
    }
}

// ---------------- launcher ---------------------------------------------------
extern "C" void kernel_launch(void* const* d_in, const int* in_sizes, int n_in,
                              void* d_out, int out_size)
{
    const float* z1ss    = (const float*)d_in[0];
    const float* uss     = (const float*)d_in[1];
    const float* z0      = (const float*)d_in[2];
    const float* pos_emb = (const float*)d_in[3];
    const float* qkv_w   = (const float*)d_in[4];
    const float* r_w     = (const float*)d_in[5];
    const float* r_w_bias= (const float*)d_in[6];
    const float* r_r_bias= (const float*)d_in[7];
    const float* o_w     = (const float*)d_in[8];
    const float* o_b     = (const float*)d_in[9];
    const float* ff1_w   = (const float*)d_in[10];
    const float* ff1_b   = (const float*)d_in[11];
    const float* ff2_w   = (const float*)d_in[12];
    const float* ff2_b   = (const float*)d_in[13];
    float* out = (float*)d_out;

    float *cat, *wheads, *rk, *avec, *tmp1, *x, *h, *tmp2;
    cudaGetSymbolAddress((void**)&cat,    g_cat);
    cudaGetSymbolAddress((void**)&wheads, g_wheads);
    cudaGetSymbolAddress((void**)&rk,     g_rk);
    cudaGetSymbolAddress((void**)&avec,   g_attnvec);
    cudaGetSymbolAddress((void**)&tmp1,   g_tmp1);
    cudaGetSymbolAddress((void**)&x,      g_x);
    cudaGetSymbolAddress((void**)&h,      g_h);
    cudaGetSymbolAddress((void**)&tmp2,   g_tmp2);

    // 1. cat = [z0 | z1ss]
    cat_kernel<<<(BSZ * D_MODEL * KLEN + 255) / 256, 256>>>(z0, z1ss);

    // 2. w_heads = qkv_w @ cat + uss          (M=3072, N=1024, K=1024, batched)
    gemm_kernel<<<dim3(KLEN / 64, 3 * D_MODEL / 128, BSZ), 256>>>(
        qkv_w, cat, wheads, nullptr, uss,
        3 * D_MODEL, KLEN, D_MODEL,
        (long)D_MODEL * KLEN, (long)3 * D_MODEL * KLEN, (long)3 * D_MODEL * KLEN, 0);

    // 3. r_head_k = r_w @ pos_emb[0]          (M=1024, N=1024, K=1024)
    gemm_kernel<<<dim3(KLEN / 64, D_MODEL / 128, 1), 256>>>(
        r_w, pos_emb, rk, nullptr, nullptr,
        D_MODEL, KLEN, D_MODEL, 0, 0, 0, 0);

    // 4. banded attention -> attn_vec (b, 1024, 512)
    attn_kernel<<<dim3(QLEN, NHEAD, BSZ), 256>>>(wheads, rk, r_w_bias, r_r_bias, avec);

    // 5. tmp1 = o_w @ attn_vec + o_b + z1ss   (M=1024, N=512, K=1024)
    gemm_kernel<<<dim3(QLEN / 64, D_MODEL / 128, BSZ), 256>>>(
        o_w, avec, tmp1, o_b, z1ss,
        D_MODEL, QLEN, D_MODEL,
        (long)D_MODEL * QLEN, (long)D_MODEL * QLEN, (long)D_MODEL * QLEN, 0);

    // 6. x = LayerNorm_channels(tmp1)
    ln_kernel<<<dim3(QLEN / 32, BSZ), 256>>>(tmp1, x);

    // 7. h = relu(ff1_w @ x + ff1_b)          (M=4096, N=512, K=1024)
    gemm_kernel<<<dim3(QLEN / 64, DINNER / 128, BSZ), 256>>>(
        ff1_w, x, h, ff1_b, nullptr,
        DINNER, QLEN, D_MODEL,
        (long)D_MODEL * QLEN, (long)DINNER * QLEN, 0, 1);

    // 8. tmp2 = ff2_w @ h + ff2_b + x         (M=1024, N=512, K=4096)
    gemm_kernel<<<dim3(QLEN / 64, D_MODEL / 128, BSZ), 256>>>(
        ff2_w, h, tmp2, ff2_b, x,
        D_MODEL, QLEN, DINNER,
        (long)DINNER * QLEN, (long)D_MODEL * QLEN, (long)D_MODEL * QLEN, 0);

    // 9. out = LayerNorm_channels(tmp2)
    ln_kernel<<<dim3(QLEN / 32, BSZ), 256>>>(tmp2, out);
}

// round 2
// speedup vs baseline: 1.0036x; 1.0036x over previous
#include <cuda_runtime.h>
#include <cuda_bf16.h>

#define BSZ     4
#define D_MODEL 1024
#define QLEN    512
#define MLEN    512
#define KLEN    1024
#define NHEAD   16
#define DHEAD   64
#define DINNER  4096
#define LOCALSZ 256

// ---------------- scratch (device globals; no allocations allowed) ----------
__device__ float g_cat[BSZ * D_MODEL * KLEN];              // 16 MB
__device__ float g_wheads[BSZ * 3 * D_MODEL * KLEN];       // 48 MB
__device__ float g_rk[D_MODEL * KLEN];                     // 4 MB
__device__ float g_attnvec[BSZ * D_MODEL * QLEN];          // 8 MB
__device__ float g_tmp1[BSZ * D_MODEL * QLEN];             // 8 MB
__device__ float g_x[BSZ * D_MODEL * QLEN];                // 8 MB
__device__ float g_h[BSZ * DINNER * QLEN];                 // 32 MB
__device__ float g_tmp2[BSZ * D_MODEL * QLEN];             // 8 MB

// ---------------- concat [z0 | z1ss] along time ------------------------------
__global__ void cat_kernel(const float* __restrict__ z0,
                           const float* __restrict__ z1ss)
{
    long idx = (long)blockIdx.x * 256 + threadIdx.x;
    if (idx >= (long)BSZ * D_MODEL * KLEN) return;
    int  t  = (int)(idx & (KLEN - 1));
    long bd = idx >> 10;                 // b*D_MODEL + d
    if (t < MLEN) g_cat[idx] = z0[bd * MLEN + t];
    else          g_cat[idx] = z1ss[bd * QLEN + (t - MLEN)];
}

// ---------------- generic SGEMM: C = A(MxK) * B(KxN) [+bias][+addend][relu] --
// A row-major (shared across batch), B/C/addend batched row-major.
__global__ __launch_bounds__(256)
void gemm_kernel(const float* __restrict__ A,
                 const float* __restrict__ B,
                 float*       __restrict__ C,
                 const float* __restrict__ bias,
                 const float* __restrict__ addend,
                 int M, int N, int K,
                 long strideB, long strideC, long strideAdd,
                 int relu)
{
    const int BM = 128, BN = 64, BK = 16;
    __shared__ float As[BK][BM + 4];
    __shared__ float Bs[BK][BN];

    int tid = threadIdx.x;
    int bn  = blockIdx.x * BN;
    int bm  = blockIdx.y * BM;
    int bz  = blockIdx.z;
    const float* Bb = B + (long)bz * strideB;

    float acc[8][4];
#pragma unroll
    for (int r = 0; r < 8; r++)
#pragma unroll
        for (int c = 0; c < 4; c++) acc[r][c] = 0.f;

    int a_k = tid & 15;          // 0..15
    int a_m = tid >> 4;          // 0..15
    int b_n = tid & 63;          // 0..63
    int b_k = tid >> 6;          // 0..3
    int tx  = tid & 15;          // n sub-tile
    int ty  = tid >> 4;          // m sub-tile

    for (int k0 = 0; k0 < K; k0 += BK) {
#pragma unroll
        for (int i = 0; i < 8; i++) {
            int m = a_m + i * 16;
            As[a_k][m] = A[(long)(bm + m) * K + (k0 + a_k)];
        }
#pragma unroll
        for (int i = 0; i < 4; i++) {
            int k = b_k + i * 4;
            Bs[k][b_n] = Bb[(long)(k0 + k) * N + (bn + b_n)];
        }
        __syncthreads();
#pragma unroll
        for (int kk = 0; kk < BK; kk++) {
            float a[8], bb[4];
#pragma unroll
            for (int r = 0; r < 8; r++) a[r] = As[kk][ty * 8 + r];
#pragma unroll
            for (int c = 0; c < 4; c++) bb[c] = Bs[kk][tx * 4 + c];
#pragma unroll
            for (int r = 0; r < 8; r++)
#pragma unroll
                for (int c = 0; c < 4; c++)
                    acc[r][c] += a[r] * bb[c];
        }
        __syncthreads();
    }

    float* Cb = C + (long)bz * strideC;
    const float* Ad = addend ? (addend + (long)bz * strideAdd) : nullptr;
#pragma unroll
    for (int r = 0; r < 8; r++) {
        int m = bm + ty * 8 + r;
        float bv = bias ? bias[m] : 0.f;
#pragma unroll
        for (int c = 0; c < 4; c++) {
            int n = bn + tx * 4 + c;
            float v = acc[r][c] + bv;
            if (Ad)  v += Ad[(long)m * N + n];
            if (relu) v = fmaxf(v, 0.f);
            Cb[(long)m * N + n] = v;
        }
    }
}

// ---------------- banded attention ------------------------------------------
// Valid keys for query i: j in [i+257, i+512] (exactly 256).
// BD[i,j] = raw_bd[i, j-i+511]  ->  r_head_k column r = 768 + j' (i-independent).
__global__ __launch_bounds__(256)
void attn_kernel(const float* __restrict__ wheads,
                 const float* __restrict__ rk,
                 const float* __restrict__ rwb,
                 const float* __restrict__ rrb,
                 float*       __restrict__ avec)
{
    int i = blockIdx.x;          // query 0..511
    int h = blockIdx.y;          // head  0..15
    int b = blockIdx.z;          // batch 0..3
    int tid = threadIdx.x;       // 0..255

    __shared__ float qw[DHEAD], qr[DHEAD];
    __shared__ float sc[256];
    __shared__ float red[256];
    __shared__ float part[256];

    const float* W = wheads + (long)b * (3 * D_MODEL) * KLEN;

    if (tid < DHEAD) {
        float qv = W[(long)(h * DHEAD + tid) * KLEN + (MLEN + i)];
        qw[tid] = qv + rwb[h * DHEAD + tid];
        qr[tid] = qv + rrb[h * DHEAD + tid];
    }
    __syncthreads();

    // scores for j = i + 257 + tid
    {
        int j = i + 257 + tid;
        const float* Kp = W + (long)(D_MODEL + h * DHEAD) * KLEN + j;
        const float* Rp = rk + (long)(h * DHEAD) * KLEN + (768 + tid);
        float ac = 0.f, bd = 0.f;
#pragma unroll 8
        for (int d = 0; d < DHEAD; d++) {
            ac += qw[d] * Kp[(long)d * KLEN];
            bd += qr[d] * Rp[(long)d * KLEN];
        }
        float s = (ac + bd) * 0.125f;   // 1/sqrt(64)
        sc[tid] = s;
        red[tid] = s;
    }
    __syncthreads();
    for (int s = 128; s > 0; s >>= 1) {
        if (tid < s) red[tid] = fmaxf(red[tid], red[tid + s]);
        __syncthreads();
    }
    float mx = red[0];
    __syncthreads();
    float p = __expf(sc[tid] - mx);
    red[tid] = p;
    __syncthreads();
    for (int s = 128; s > 0; s >>= 1) {
        if (tid < s) red[tid] += red[tid + s];
        __syncthreads();
    }
    float inv = 1.0f / red[0];
    __syncthreads();
    sc[tid] = p * inv;
    __syncthreads();

    // attn_vec: sum_j prob[j'] * V[d, i+257+j']
    {
        int d  = tid & 63;
        int pg = tid >> 6;      // 0..3
        const float* Vp = W + (long)(2 * D_MODEL + h * DHEAD + d) * KLEN + (i + 257);
        float acc = 0.f;
        int j0 = pg * 64;
#pragma unroll 8
        for (int jj = 0; jj < 64; jj++)
            acc += sc[j0 + jj] * Vp[j0 + jj];
        part[tid] = acc;
    }
    __syncthreads();
    if (tid < DHEAD) {
        float v = part[tid] + part[64 + tid] + part[128 + tid] + part[192 + tid];
        avec[(long)b * D_MODEL * QLEN + (long)(h * DHEAD + tid) * QLEN + i] = v;
    }
}

// ---------------- channel LayerNorm (over axis=1, 1024 channels) -------------
__global__ __launch_bounds__(256)
void ln_kernel(const float* __restrict__ y, float* __restrict__ out)
{
    int b  = blockIdx.y;
    int t0 = blockIdx.x * 32;
    int tid = threadIdx.x;
    int tt = tid & 31, cg = tid >> 5;    // cg 0..7, each covers 128 channels
    const float* Y = y + (long)b * D_MODEL * QLEN;

    float s = 0.f, s2 = 0.f;
    for (int c = cg * 128; c < cg * 128 + 128; c++) {
        float v = Y[(long)c * QLEN + t0 + tt];
        s += v; s2 += v * v;
    }
    __shared__ float ssum[8][32], ssq[8][32];
    __shared__ float smean[32], srstd[32];
    ssum[cg][tt] = s; ssq[cg][tt] = s2;
    __syncthreads();
    if (tid < 32) {
        float ts = 0.f, ts2 = 0.f;
#pragma unroll
        for (int g = 0; g < 8; g++) { ts += ssum[g][tid]; ts2 += ssq[g][tid]; }
        float mean = ts * (1.0f / D_MODEL);
        float var  = ts2 * (1.0f / D_MODEL) - mean * mean;
        smean[tid] = mean;
        srstd[tid] = rsqrtf(var + 1e-5f);
    }
    __syncthreads();
    float mean = smean[tt], rstd = srstd[tt];
    float* O = out + (long)b * D_MODEL * QLEN;
    for (int c = cg * 128; c < cg * 128 + 128; c++) {
        float v = Y[(long)c * QLEN + t0 + tt];
        O[(long)c * QLEN + t0 + tt] = (v - mean) * rstd;
    }
}

// ---------------- launcher ---------------------------------------------------
extern "C" void kernel_launch(void* const* d_in, const int* in_sizes, int n_in,
                              void* d_out, int out_size)
{
    const float* z1ss    = (const float*)d_in[0];
    const float* uss     = (const float*)d_in[1];
    const float* z0      = (const float*)d_in[2];
    const float* pos_emb = (const float*)d_in[3];
    const float* qkv_w   = (const float*)d_in[4];
    const float* r_w     = (const float*)d_in[5];
    const float* r_w_bias= (const float*)d_in[6];
    const float* r_r_bias= (const float*)d_in[7];
    const float* o_w     = (const float*)d_in[8];
    const float* o_b     = (const float*)d_in[9];
    const float* ff1_w   = (const float*)d_in[10];
    const float* ff1_b   = (const float*)d_in[11];
    const float* ff2_w   = (const float*)d_in[12];
    const float* ff2_b   = (const float*)d_in[13];
    float* out = (float*)d_out;

    float *cat, *wheads, *rk, *avec, *tmp1, *x, *h, *tmp2;
    cudaGetSymbolAddress((void**)&cat,    g_cat);
    cudaGetSymbolAddress((void**)&wheads, g_wheads);
    cudaGetSymbolAddress((void**)&rk,     g_rk);
    cudaGetSymbolAddress((void**)&avec,   g_attnvec);
    cudaGetSymbolAddress((void**)&tmp1,   g_tmp1);
    cudaGetSymbolAddress((void**)&x,      g_x);
    cudaGetSymbolAddress((void**)&h,      g_h);
    cudaGetSymbolAddress((void**)&tmp2,   g_tmp2);

    // 1. cat = [z0 | z1ss]
    cat_kernel<<<(BSZ * D_MODEL * KLEN + 255) / 256, 256>>>(z0, z1ss);

    // 2. w_heads = qkv_w @ cat + uss          (M=3072, N=1024, K=1024, batched)
    gemm_kernel<<<dim3(KLEN / 64, 3 * D_MODEL / 128, BSZ), 256>>>(
        qkv_w, cat, wheads, nullptr, uss,
        3 * D_MODEL, KLEN, D_MODEL,
        (long)D_MODEL * KLEN, (long)3 * D_MODEL * KLEN, (long)3 * D_MODEL * KLEN, 0);

    // 3. r_head_k = r_w @ pos_emb[0]          (M=1024, N=1024, K=1024)
    gemm_kernel<<<dim3(KLEN / 64, D_MODEL / 128, 1), 256>>>(
        r_w, pos_emb, rk, nullptr, nullptr,
        D_MODEL, KLEN, D_MODEL, 0, 0, 0, 0);

    // 4. banded attention -> attn_vec (b, 1024, 512)
    attn_kernel<<<dim3(QLEN, NHEAD, BSZ), 256>>>(wheads, rk, r_w_bias, r_r_bias, avec);

    // 5. tmp1 = o_w @ attn_vec + o_b + z1ss   (M=1024, N=512, K=1024)
    gemm_kernel<<<dim3(QLEN / 64, D_MODEL / 128, BSZ), 256>>>(
        o_w, avec, tmp1, o_b, z1ss,
        D_MODEL, QLEN, D_MODEL,
        (long)D_MODEL * QLEN, (long)D_MODEL * QLEN, (long)D_MODEL * QLEN, 0);

    // 6. x = LayerNorm_channels(tmp1)
    ln_kernel<<<dim3(QLEN / 32, BSZ), 256>>>(tmp1, x);

    // 7. h = relu(ff1_w @ x + ff1_b)          (M=4096, N=512, K=1024)
    gemm_kernel<<<dim3(QLEN / 64, DINNER / 128, BSZ), 256>>>(
        ff1_w, x, h, ff1_b, nullptr,
        DINNER, QLEN, D_MODEL,
        (long)D_MODEL * QLEN, (long)DINNER * QLEN, 0, 1);

    // 8. tmp2 = ff2_w @ h + ff2_b + x         (M=1024, N=512, K=4096)
    gemm_kernel<<<dim3(QLEN / 64, D_MODEL / 128, BSZ), 256>>>(
        ff2_w, h, tmp2, ff2_b, x,
        D_MODEL, QLEN, DINNER,
        (long)DINNER * QLEN, (long)D_MODEL * QLEN, (long)D_MODEL * QLEN, 0);

    // 9. out = LayerNorm_channels(tmp2)
    ln_kernel<<<dim3(QLEN / 32, BSZ), 256>>>(tmp2, out);
}

// round 3
// speedup vs baseline: 1.3136x; 1.3089x over previous
#include <cuda_runtime.h>
#include <cuda_bf16.h>
#include <cstdint>

#define BSZ     4
#define D_MODEL 1024
#define QLEN    512
#define MLEN    512
#define KLEN    1024
#define NHEAD   16
#define DHEAD   64
#define DINNER  4096

typedef __nv_bfloat16 bf16;

// ---------------- fp32 scratch ----------------------------------------------
__device__ float g_wheads[BSZ * 3 * D_MODEL * KLEN];       // 48 MB
__device__ float g_rk[D_MODEL * KLEN];                     // 4 MB
__device__ float g_attnvec[BSZ * D_MODEL * QLEN];          // 8 MB
__device__ float g_tmp1[BSZ * D_MODEL * QLEN];             // 8 MB
__device__ float g_x[BSZ * D_MODEL * QLEN];                // 8 MB
__device__ float g_h[BSZ * DINNER * QLEN];                 // 32 MB
__device__ float g_tmp2[BSZ * D_MODEL * QLEN];             // 8 MB

// ---------------- bf16-split (hi,hi,lo / hi,lo,hi) scratch -------------------
__device__ bf16 g_qkvw3[3 * D_MODEL * 3 * D_MODEL];        // 3072 x 3072
__device__ bf16 g_rw3  [D_MODEL * 3 * D_MODEL];            // 1024 x 3072
__device__ bf16 g_ow3  [D_MODEL * 3 * D_MODEL];            // 1024 x 3072
__device__ bf16 g_ff1w3[DINNER * 3 * D_MODEL];             // 4096 x 3072
__device__ bf16 g_ff2w3[D_MODEL * 3 * DINNER];             // 1024 x 12288
__device__ bf16 g_pos3 [3 * D_MODEL * KLEN];               // 3072 x 1024
__device__ bf16 g_cat3 [BSZ * 3 * D_MODEL * KLEN];         // b x 3072 x 1024
__device__ bf16 g_avec3[BSZ * 3 * D_MODEL * QLEN];         // b x 3072 x 512
__device__ bf16 g_x3   [BSZ * 3 * D_MODEL * QLEN];         // b x 3072 x 512
__device__ bf16 g_h3   [BSZ * 3 * DINNER * QLEN];          // b x 12288 x 512

// ---------------- helpers ----------------------------------------------------
__device__ __forceinline__ void split_bf16(float x, bf16& hi, bf16& lo)
{
    hi = __float2bfloat16(x);
    lo = __float2bfloat16(x - __bfloat162float(hi));
}

__device__ __forceinline__ void cp_async16(uint32_t smem_dst, const void* gmem_src)
{
    asm volatile("cp.async.cg.shared.global [%0], [%1], 16;\n"
                 :: "r"(smem_dst), "l"(gmem_src));
}
__device__ __forceinline__ void cp_commit()
{
    asm volatile("cp.async.commit_group;\n");
}
__device__ __forceinline__ void cp_wait_all()
{
    asm volatile("cp.async.wait_group 0;\n");
}
__device__ __forceinline__ void ldsm_x4(uint32_t& r0, uint32_t& r1, uint32_t& r2, uint32_t& r3, uint32_t addr)
{
    asm volatile("ldmatrix.sync.aligned.m8n8.x4.shared.b16 {%0,%1,%2,%3}, [%4];\n"
                 : "=r"(r0), "=r"(r1), "=r"(r2), "=r"(r3) : "r"(addr));
}
__device__ __forceinline__ void ldsm_x4_t(uint32_t& r0, uint32_t& r1, uint32_t& r2, uint32_t& r3, uint32_t addr)
{
    asm volatile("ldmatrix.sync.aligned.m8n8.x4.trans.shared.b16 {%0,%1,%2,%3}, [%4];\n"
                 : "=r"(r0), "=r"(r1), "=r"(r2), "=r"(r3) : "r"(addr));
}
__device__ __forceinline__ void mma16816(float* c, const uint32_t* a, const uint32_t* b)
{
    asm volatile(
        "mma.sync.aligned.m16n8k16.row.col.f32.bf16.bf16.f32 "
        "{%0,%1,%2,%3}, {%4,%5,%6,%7}, {%8,%9}, {%0,%1,%2,%3};\n"
        : "+f"(c[0]), "+f"(c[1]), "+f"(c[2]), "+f"(c[3])
        : "r"(a[0]), "r"(a[1]), "r"(a[2]), "r"(a[3]), "r"(b[0]), "r"(b[1]));
}

// ---------------- expansion kernels ------------------------------------------
// A-pattern: in M x K row-major -> out M x 3K with [hi, hi, lo] per k.
__global__ void expandA_kernel(const float* __restrict__ in, bf16* __restrict__ out, int K)
{
    int k = blockIdx.x * 256 + threadIdx.x;
    int m = blockIdx.y;
    float x = in[(long)m * K + k];
    bf16 hi, lo; split_bf16(x, hi, lo);
    bf16* o = out + (long)m * 3 * K + 3 * k;
    o[0] = hi; o[1] = hi; o[2] = lo;
}

// B-pattern: in K x N row-major (batched) -> out 3K x N with rows [hi, lo, hi].
__global__ void expandB_kernel(const float* __restrict__ in, bf16* __restrict__ out,
                               int N, long sIn, long sOut)
{
    int n = blockIdx.x * 256 + threadIdx.x;
    int k = blockIdx.y;
    float x = in[(long)blockIdx.z * sIn + (long)k * N + n];
    bf16 hi, lo; split_bf16(x, hi, lo);
    bf16* o = out + (long)blockIdx.z * sOut + (long)(3 * k) * N + n;
    o[0] = hi; o[N] = lo; o[2 * N] = hi;
}

// cat expansion: builds cat3 (b, 3*1024, 1024) directly from z0|z1ss.
__global__ void expand_cat_kernel(const float* __restrict__ z0, const float* __restrict__ z1ss)
{
    int t = blockIdx.x * 256 + threadIdx.x;
    int d = blockIdx.y;
    int b = blockIdx.z;
    float x = (t < MLEN) ? z0[((long)b * D_MODEL + d) * MLEN + t]
                         : z1ss[((long)b * D_MODEL + d) * QLEN + (t - MLEN)];
    bf16 hi, lo; split_bf16(x, hi, lo);
    bf16* o = g_cat3 + (long)b * 3 * D_MODEL * KLEN + (long)(3 * d) * KLEN + t;
    o[0] = hi; o[KLEN] = lo; o[2 * KLEN] = hi;
}

// ---------------- tensor-core GEMM ------------------------------------------
// C(MxN fp32) = A3(Mx3K bf16, shared) * B3(3KxN bf16, batched) [+bias][+addend][relu]
#define GBM 128
#define GBN 128
#define GBK 32
#define APAD 40
#define BPAD 136

__global__ __launch_bounds__(256)
void gemm_bf16_kernel(const bf16* __restrict__ A,
                      const bf16* __restrict__ B,
                      float*      __restrict__ C,
                      const float* __restrict__ bias,
                      const float* __restrict__ addend,
                      int M, int N, int K,            // K = expanded (3x) K
                      long strideB, long strideC, long strideAdd,
                      int relu)
{
    __shared__ bf16 As[2][GBM * APAD];
    __shared__ bf16 Bs[2][GBK * BPAD];

    const int tid  = threadIdx.x;
    const int lane = tid & 31;
    const int warp = tid >> 5;
    const int wm = warp >> 2;          // 0..1
    const int wn = warp & 3;           // 0..3
    const int bn = blockIdx.x * GBN;
    const int bm = blockIdx.y * GBM;

    const bf16* Ag = A + (long)bm * K;
    const bf16* Bg = B + (long)blockIdx.z * strideB;

    uint32_t sA = (uint32_t)__cvta_generic_to_shared(&As[0][0]);
    uint32_t sB = (uint32_t)__cvta_generic_to_shared(&Bs[0][0]);
    const uint32_t sAsz = GBM * APAD * 2;
    const uint32_t sBsz = GBK * BPAD * 2;

    float acc[4][4][4];
#pragma unroll
    for (int i = 0; i < 4; i++)
#pragma unroll
        for (int j = 0; j < 4; j++)
#pragma unroll
            for (int r = 0; r < 4; r++) acc[i][j][r] = 0.f;

    // load tile (buf, k0)
    auto load_tiles = [&](int buf, int k0) {
#pragma unroll
        for (int i = 0; i < 2; i++) {
            int c   = tid + 256 * i;       // 512 chunks of 16B for A
            int row = c >> 2, ch = c & 3;
            cp_async16(sA + buf * sAsz + (row * APAD + ch * 8) * 2,
                       Ag + (long)row * K + k0 + ch * 8);
        }
#pragma unroll
        for (int i = 0; i < 2; i++) {
            int c   = tid + 256 * i;       // 512 chunks of 16B for B
            int row = c >> 4, ch = c & 15;
            cp_async16(sB + buf * sBsz + (row * BPAD + ch * 8) * 2,
                       Bg + (long)(k0 + row) * N + bn + ch * 8);
        }
        cp_commit();
    };

    load_tiles(0, 0);

    const int nIter = K / GBK;
    for (int it = 0; it < nIter; it++) {
        int buf = it & 1;
        cp_wait_all();
        __syncthreads();
        if (it + 1 < nIter) load_tiles(buf ^ 1, (it + 1) * GBK);

        // compute on buf
#pragma unroll
        for (int ks = 0; ks < 2; ks++) {
            uint32_t afrag[4][4];
            uint32_t bfrag[4][2];
            int lrow = lane & 15, lcol = (lane >> 4) * 8;
#pragma unroll
            for (int mi = 0; mi < 4; mi++) {
                uint32_t addr = sA + buf * sAsz +
                    ((64 * wm + 16 * mi + lrow) * APAD + ks * 16 + lcol) * 2;
                ldsm_x4(afrag[mi][0], afrag[mi][1], afrag[mi][2], afrag[mi][3], addr);
            }
#pragma unroll
            for (int nj2 = 0; nj2 < 2; nj2++) {
                uint32_t addr = sB + buf * sBsz +
                    ((ks * 16 + lrow) * BPAD + 32 * wn + 16 * nj2 + lcol) * 2;
                uint32_t r0, r1, r2, r3;
                ldsm_x4_t(r0, r1, r2, r3, addr);
                bfrag[2 * nj2][0] = r0;     bfrag[2 * nj2][1] = r1;
                bfrag[2 * nj2 + 1][0] = r2; bfrag[2 * nj2 + 1][1] = r3;
            }
#pragma unroll
            for (int mi = 0; mi < 4; mi++)
#pragma unroll
                for (int nj = 0; nj < 4; nj++)
                    mma16816(acc[mi][nj], afrag[mi], bfrag[nj]);
        }
        __syncthreads();
    }

    // epilogue
    float* Cb = C + (long)blockIdx.z * strideC;
    const float* Ad = addend ? (addend + (long)blockIdx.z * strideAdd) : nullptr;
    int g = lane >> 2, tg = lane & 3;
#pragma unroll
    for (int mi = 0; mi < 4; mi++) {
        int row0 = bm + 64 * wm + 16 * mi + g;
        int row1 = row0 + 8;
        float bv0 = bias ? bias[row0] : 0.f;
        float bv1 = bias ? bias[row1] : 0.f;
#pragma unroll
        for (int nj = 0; nj < 4; nj++) {
            int col = bn + 32 * wn + 8 * nj + 2 * tg;
            float v00 = acc[mi][nj][0] + bv0;
            float v01 = acc[mi][nj][1] + bv0;
            float v10 = acc[mi][nj][2] + bv1;
            float v11 = acc[mi][nj][3] + bv1;
            if (Ad) {
                v00 += Ad[(long)row0 * N + col];
                v01 += Ad[(long)row0 * N + col + 1];
                v10 += Ad[(long)row1 * N + col];
                v11 += Ad[(long)row1 * N + col + 1];
            }
            if (relu) {
                v00 = fmaxf(v00, 0.f); v01 = fmaxf(v01, 0.f);
                v10 = fmaxf(v10, 0.f); v11 = fmaxf(v11, 0.f);
            }
            Cb[(long)row0 * N + col]     = v00;
            Cb[(long)row0 * N + col + 1] = v01;
            Cb[(long)row1 * N + col]     = v10;
            Cb[(long)row1 * N + col + 1] = v11;
        }
    }
}

// ---------------- banded attention ------------------------------------------
// Valid keys for query i: j in [i+257, i+512] (exactly 256).
// BD[i,j] = raw_bd[i, j-i+511]  ->  r_head_k column r = 768 + j' (i-independent).
__global__ __launch_bounds__(256)
void attn_kernel(const float* __restrict__ wheads,
                 const float* __restrict__ rk,
                 const float* __restrict__ rwb,
                 const float* __restrict__ rrb,
                 float*       __restrict__ avec)
{
    int i = blockIdx.x;
    int h = blockIdx.y;
    int b = blockIdx.z;
    int tid = threadIdx.x;

    __shared__ float qw[DHEAD], qr[DHEAD];
    __shared__ float sc[256];
    __shared__ float red[256];
    __shared__ float part[256];

    const float* W = wheads + (long)b * (3 * D_MODEL) * KLEN;

    if (tid < DHEAD) {
        float qv = W[(long)(h * DHEAD + tid) * KLEN + (MLEN + i)];
        qw[tid] = qv + rwb[h * DHEAD + tid];
        qr[tid] = qv + rrb[h * DHEAD + tid];
    }
    __syncthreads();

    {
        int j = i + 257 + tid;
        const float* Kp = W + (long)(D_MODEL + h * DHEAD) * KLEN + j;
        const float* Rp = rk + (long)(h * DHEAD) * KLEN + (768 + tid);
        float ac = 0.f, bd = 0.f;
#pragma unroll 8
        for (int d = 0; d < DHEAD; d++) {
            ac += qw[d] * Kp[(long)d * KLEN];
            bd += qr[d] * Rp[(long)d * KLEN];
        }
        float s = (ac + bd) * 0.125f;
        sc[tid] = s;
        red[tid] = s;
    }
    __syncthreads();
    for (int s = 128; s > 0; s >>= 1) {
        if (tid < s) red[tid] = fmaxf(red[tid], red[tid + s]);
        __syncthreads();
    }
    float mx = red[0];
    __syncthreads();
    float p = __expf(sc[tid] - mx);
    red[tid] = p;
    __syncthreads();
    for (int s = 128; s > 0; s >>= 1) {
        if (tid < s) red[tid] += red[tid + s];
        __syncthreads();
    }
    float inv = 1.0f / red[0];
    __syncthreads();
    sc[tid] = p * inv;
    __syncthreads();

    {
        int d  = tid & 63;
        int pg = tid >> 6;
        const float* Vp = W + (long)(2 * D_MODEL + h * DHEAD + d) * KLEN + (i + 257);
        float a = 0.f;
        int j0 = pg * 64;
#pragma unroll 8
        for (int jj = 0; jj < 64; jj++)
            a += sc[j0 + jj] * Vp[j0 + jj];
        part[tid] = a;
    }
    __syncthreads();
    if (tid < DHEAD) {
        float v = part[tid] + part[64 + tid] + part[128 + tid] + part[192 + tid];
        avec[(long)b * D_MODEL * QLEN + (long)(h * DHEAD + tid) * QLEN + i] = v;
    }
}

// ---------------- channel LayerNorm (over axis=1, 1024 channels) -------------
__global__ __launch_bounds__(256)
void ln_kernel(const float* __restrict__ y, float* __restrict__ out)
{
    int b  = blockIdx.y;
    int t0 = blockIdx.x * 32;
    int tid = threadIdx.x;
    int tt = tid & 31, cg = tid >> 5;
    const float* Y = y + (long)b * D_MODEL * QLEN;

    float s = 0.f, s2 = 0.f;
    for (int c = cg * 128; c < cg * 128 + 128; c++) {
        float v = Y[(long)c * QLEN + t0 + tt];
        s += v; s2 += v * v;
    }
    __shared__ float ssum[8][32], ssq[8][32];
    __shared__ float smean[32], srstd[32];
    ssum[cg][tt] = s; ssq[cg][tt] = s2;
    __syncthreads();
    if (tid < 32) {
        float ts = 0.f, ts2 = 0.f;
#pragma unroll
        for (int g = 0; g < 8; g++) { ts += ssum[g][tid]; ts2 += ssq[g][tid]; }
        float mean = ts * (1.0f / D_MODEL);
        float var  = ts2 * (1.0f / D_MODEL) - mean * mean;
        smean[tid] = mean;
        srstd[tid] = rsqrtf(var + 1e-5f);
    }
    __syncthreads();
    float mean = smean[tt], rstd = srstd[tt];
    float* O = out + (long)b * D_MODEL * QLEN;
    for (int c = cg * 128; c < cg * 128 + 128; c++) {
        float v = Y[(long)c * QLEN + t0 + tt];
        O[(long)c * QLEN + t0 + tt] = (v - mean) * rstd;
    }
}

// ---------------- launcher ---------------------------------------------------
extern "C" void kernel_launch(void* const* d_in, const int* in_sizes, int n_in,
                              void* d_out, int out_size)
{
    const float* z1ss    = (const float*)d_in[0];
    const float* uss     = (const float*)d_in[1];
    const float* z0      = (const float*)d_in[2];
    const float* pos_emb = (const float*)d_in[3];
    const float* qkv_w   = (const float*)d_in[4];
    const float* r_w     = (const float*)d_in[5];
    const float* r_w_bias= (const float*)d_in[6];
    const float* r_r_bias= (const float*)d_in[7];
    const float* o_w     = (const float*)d_in[8];
    const float* o_b     = (const float*)d_in[9];
    const float* ff1_w   = (const float*)d_in[10];
    const float* ff1_b   = (const float*)d_in[11];
    const float* ff2_w   = (const float*)d_in[12];
    const float* ff2_b   = (const float*)d_in[13];
    float* out = (float*)d_out;

    float *wheads, *rk, *avec, *tmp1, *x, *h, *tmp2;
    bf16 *qkvw3, *rw3, *ow3, *ff1w3, *ff2w3, *pos3, *cat3, *avec3, *x3, *h3;
    cudaGetSymbolAddress((void**)&wheads, g_wheads);
    cudaGetSymbolAddress((void**)&rk,     g_rk);
    cudaGetSymbolAddress((void**)&avec,   g_attnvec);
    cudaGetSymbolAddress((void**)&tmp1,   g_tmp1);
    cudaGetSymbolAddress((void**)&x,      g_x);
    cudaGetSymbolAddress((void**)&h,      g_h);
    cudaGetSymbolAddress((void**)&tmp2,   g_tmp2);
    cudaGetSymbolAddress((void**)&qkvw3,  g_qkvw3);
    cudaGetSymbolAddress((void**)&rw3,    g_rw3);
    cudaGetSymbolAddress((void**)&ow3,    g_ow3);
    cudaGetSymbolAddress((void**)&ff1w3,  g_ff1w3);
    cudaGetSymbolAddress((void**)&ff2w3,  g_ff2w3);
    cudaGetSymbolAddress((void**)&pos3,   g_pos3);
    cudaGetSymbolAddress((void**)&cat3,   g_cat3);
    cudaGetSymbolAddress((void**)&avec3,  g_avec3);
    cudaGetSymbolAddress((void**)&x3,     g_x3);
    cudaGetSymbolAddress((void**)&h3,     g_h3);

    // ---- operand expansions (weights + static inputs) ----
    expandA_kernel<<<dim3(D_MODEL / 256, 3 * D_MODEL), 256>>>(qkv_w, qkvw3, D_MODEL);
    expandA_kernel<<<dim3(D_MODEL / 256, D_MODEL),     256>>>(r_w,   rw3,   D_MODEL);
    expandA_kernel<<<dim3(D_MODEL / 256, D_MODEL),     256>>>(o_w,   ow3,   D_MODEL);
    expandA_kernel<<<dim3(D_MODEL / 256, DINNER),      256>>>(ff1_w, ff1w3, D_MODEL);
    expandA_kernel<<<dim3(DINNER / 256,  D_MODEL),     256>>>(ff2_w, ff2w3, DINNER);
    expandB_kernel<<<dim3(KLEN / 256, D_MODEL, 1), 256>>>(pos_emb, pos3, KLEN, 0, 0);
    expand_cat_kernel<<<dim3(KLEN / 256, D_MODEL, BSZ), 256>>>(z0, z1ss);

    // ---- QKV: wheads = qkv_w @ cat + uss  (M=3072, N=1024, K'=3072) ----
    gemm_bf16_kernel<<<dim3(KLEN / GBN, 3 * D_MODEL / GBM, BSZ), 256>>>(
        qkvw3, cat3, wheads, nullptr, uss,
        3 * D_MODEL, KLEN, 3 * D_MODEL,
        (long)3 * D_MODEL * KLEN, (long)3 * D_MODEL * KLEN, (long)3 * D_MODEL * KLEN, 0);

    // ---- r_head_k = r_w @ pos_emb  (M=1024, N=1024, K'=3072) ----
    gemm_bf16_kernel<<<dim3(KLEN / GBN, D_MODEL / GBM, 1), 256>>>(
        rw3, pos3, rk, nullptr, nullptr,
        D_MODEL, KLEN, 3 * D_MODEL, 0, 0, 0, 0);

    // ---- banded attention ----
    attn_kernel<<<dim3(QLEN, NHEAD, BSZ), 256>>>(wheads, rk, r_w_bias, r_r_bias, avec);

    // ---- O-proj: tmp1 = o_w @ avec + o_b + z1ss ----
    expandB_kernel<<<dim3(QLEN / 256, D_MODEL, BSZ), 256>>>(
        avec, avec3, QLEN, (long)D_MODEL * QLEN, (long)3 * D_MODEL * QLEN);
    gemm_bf16_kernel<<<dim3(QLEN / GBN, D_MODEL / GBM, BSZ), 256>>>(
        ow3, avec3, tmp1, o_b, z1ss,
        D_MODEL, QLEN, 3 * D_MODEL,
        (long)3 * D_MODEL * QLEN, (long)D_MODEL * QLEN, (long)D_MODEL * QLEN, 0);

    // ---- x = LN(tmp1) ----
    ln_kernel<<<dim3(QLEN / 32, BSZ), 256>>>(tmp1, x);

    // ---- FF1: h = relu(ff1_w @ x + ff1_b) ----
    expandB_kernel<<<dim3(QLEN / 256, D_MODEL, BSZ), 256>>>(
        x, x3, QLEN, (long)D_MODEL * QLEN, (long)3 * D_MODEL * QLEN);
    gemm_bf16_kernel<<<dim3(QLEN / GBN, DINNER / GBM, BSZ), 256>>>(
        ff1w3, x3, h, ff1_b, nullptr,
        DINNER, QLEN, 3 * D_MODEL,
        (long)3 * D_MODEL * QLEN, (long)DINNER * QLEN, 0, 1);

    // ---- FF2: tmp2 = ff2_w @ h + ff2_b + x ----
    expandB_kernel<<<dim3(QLEN / 256, DINNER, BSZ), 256>>>(
        h, h3, QLEN, (long)DINNER * QLEN, (long)3 * DINNER * QLEN);
    gemm_bf16_kernel<<<dim3(QLEN / GBN, D_MODEL / GBM, BSZ), 256>>>(
        ff2w3, h3, tmp2, ff2_b, x,
        D_MODEL, QLEN, 3 * DINNER,
        (long)3 * DINNER * QLEN, (long)D_MODEL * QLEN, (long)D_MODEL * QLEN, 0);

    // ---- out = LN(tmp2) ----
    ln_kernel<<<dim3(QLEN / 32, BSZ), 256>>>(tmp2, out);
}

// round 5
// speedup vs baseline: 2.9649x; 2.2571x over previous
#include <cuda_runtime.h>
#include <cuda_bf16.h>
#include <cstdint>

#define BSZ     4
#define D_MODEL 1024
#define QLEN    512
#define MLEN    512
#define KLEN    1024
#define NHEAD   16
#define DHEAD   64
#define DINNER  4096

typedef __nv_bfloat16 bf16;

// ---------------- fp32 scratch ----------------------------------------------
__device__ float g_wheads[BSZ * 3 * D_MODEL * KLEN];       // 48 MB
__device__ float g_rk[D_MODEL * KLEN];                     // 4 MB
__device__ float g_attnvec[BSZ * D_MODEL * QLEN];          // 8 MB
__device__ float g_tmp1[BSZ * D_MODEL * QLEN];             // 8 MB
__device__ float g_x[BSZ * D_MODEL * QLEN];                // 8 MB
__device__ float g_h[BSZ * DINNER * QLEN];                 // 32 MB
__device__ float g_tmp2[BSZ * D_MODEL * QLEN];             // 8 MB

// ---------------- bf16-split (hi,hi,lo / hi,lo,hi) scratch -------------------
__device__ bf16 g_qkvw3[3 * D_MODEL * 3 * D_MODEL];
__device__ bf16 g_rw3  [D_MODEL * 3 * D_MODEL];
__device__ bf16 g_ow3  [D_MODEL * 3 * D_MODEL];
__device__ bf16 g_ff1w3[DINNER * 3 * D_MODEL];
__device__ bf16 g_ff2w3[D_MODEL * 3 * DINNER];
__device__ bf16 g_pos3 [3 * D_MODEL * KLEN];
__device__ bf16 g_cat3 [BSZ * 3 * D_MODEL * KLEN];
__device__ bf16 g_avec3[BSZ * 3 * D_MODEL * QLEN];
__device__ bf16 g_x3   [BSZ * 3 * D_MODEL * QLEN];
__device__ bf16 g_h3   [BSZ * 3 * DINNER * QLEN];

// ---------------- helpers ----------------------------------------------------
__device__ __forceinline__ void split_bf16(float x, bf16& hi, bf16& lo)
{
    hi = __float2bfloat16(x);
    lo = __float2bfloat16(x - __bfloat162float(hi));
}

__device__ __forceinline__ void cp_async16(uint32_t smem_dst, const void* gmem_src)
{
    asm volatile("cp.async.cg.shared.global [%0], [%1], 16;\n"
                 :: "r"(smem_dst), "l"(gmem_src));
}
__device__ __forceinline__ void cp_commit()
{
    asm volatile("cp.async.commit_group;\n");
}
__device__ __forceinline__ void cp_wait_all()
{
    asm volatile("cp.async.wait_group 0;\n");
}
__device__ __forceinline__ void ldsm_x4(uint32_t& r0, uint32_t& r1, uint32_t& r2, uint32_t& r3, uint32_t addr)
{
    asm volatile("ldmatrix.sync.aligned.m8n8.x4.shared.b16 {%0,%1,%2,%3}, [%4];\n"
                 : "=r"(r0), "=r"(r1), "=r"(r2), "=r"(r3) : "r"(addr));
}
__device__ __forceinline__ void ldsm_x4_t(uint32_t& r0, uint32_t& r1, uint32_t& r2, uint32_t& r3, uint32_t addr)
{
    asm volatile("ldmatrix.sync.aligned.m8n8.x4.trans.shared.b16 {%0,%1,%2,%3}, [%4];\n"
                 : "=r"(r0), "=r"(r1), "=r"(r2), "=r"(r3) : "r"(addr));
}
__device__ __forceinline__ void mma16816(float* c, const uint32_t* a, const uint32_t* b)
{
    asm volatile(
        "mma.sync.aligned.m16n8k16.row.col.f32.bf16.bf16.f32 "
        "{%0,%1,%2,%3}, {%4,%5,%6,%7}, {%8,%9}, {%0,%1,%2,%3};\n"
        : "+f"(c[0]), "+f"(c[1]), "+f"(c[2]), "+f"(c[3])
        : "r"(a[0]), "r"(a[1]), "r"(a[2]), "r"(a[3]), "r"(b[0]), "r"(b[1]));
}

// ---------------- expansion kernels ------------------------------------------
__global__ void expandA_kernel(const float* __restrict__ in, bf16* __restrict__ out, int K)
{
    int k = blockIdx.x * 256 + threadIdx.x;
    int m = blockIdx.y;
    float x = in[(long)m * K + k];
    bf16 hi, lo; split_bf16(x, hi, lo);
    bf16* o = out + (long)m * 3 * K + 3 * k;
    o[0] = hi; o[1] = hi; o[2] = lo;
}

__global__ void expandB_kernel(const float* __restrict__ in, bf16* __restrict__ out,
                               int N, long sIn, long sOut)
{
    int n = blockIdx.x * 256 + threadIdx.x;
    int k = blockIdx.y;
    float x = in[(long)blockIdx.z * sIn + (long)k * N + n];
    bf16 hi, lo; split_bf16(x, hi, lo);
    bf16* o = out + (long)blockIdx.z * sOut + (long)(3 * k) * N + n;
    o[0] = hi; o[N] = lo; o[2 * N] = hi;
}

__global__ void expand_cat_kernel(const float* __restrict__ z0, const float* __restrict__ z1ss)
{
    int t = blockIdx.x * 256 + threadIdx.x;
    int d = blockIdx.y;
    int b = blockIdx.z;
    float x = (t < MLEN) ? z0[((long)b * D_MODEL + d) * MLEN + t]
                         : z1ss[((long)b * D_MODEL + d) * QLEN + (t - MLEN)];
    bf16 hi, lo; split_bf16(x, hi, lo);
    bf16* o = g_cat3 + (long)b * 3 * D_MODEL * KLEN + (long)(3 * d) * KLEN + t;
    o[0] = hi; o[KLEN] = lo; o[2 * KLEN] = hi;
}

// ---------------- tensor-core GEMM (mma.sync, known-good) --------------------
#define GBM 128
#define GBN 128
#define GBK 32
#define APAD 40
#define BPAD 136

__global__ __launch_bounds__(256)
void gemm_bf16_kernel(const bf16* __restrict__ A,
                      const bf16* __restrict__ B,
                      float*      __restrict__ C,
                      const float* __restrict__ bias,
                      const float* __restrict__ addend,
                      int M, int N, int K,
                      long strideB, long strideC, long strideAdd,
                      int relu)
{
    __shared__ bf16 As[2][GBM * APAD];
    __shared__ bf16 Bs[2][GBK * BPAD];

    const int tid  = threadIdx.x;
    const int lane = tid & 31;
    const int warp = tid >> 5;
    const int wm = warp >> 2;
    const int wn = warp & 3;
    const int bn = blockIdx.x * GBN;
    const int bm = blockIdx.y * GBM;

    const bf16* Ag = A + (long)bm * K;
    const bf16* Bg = B + (long)blockIdx.z * strideB;

    uint32_t sA = (uint32_t)__cvta_generic_to_shared(&As[0][0]);
    uint32_t sB = (uint32_t)__cvta_generic_to_shared(&Bs[0][0]);
    const uint32_t sAsz = GBM * APAD * 2;
    const uint32_t sBsz = GBK * BPAD * 2;

    float acc[4][4][4];
#pragma unroll
    for (int i = 0; i < 4; i++)
#pragma unroll
        for (int j = 0; j < 4; j++)
#pragma unroll
            for (int r = 0; r < 4; r++) acc[i][j][r] = 0.f;

    auto load_tiles = [&](int buf, int k0) {
#pragma unroll
        for (int i = 0; i < 2; i++) {
            int c   = tid + 256 * i;
            int row = c >> 2, ch = c & 3;
            cp_async16(sA + buf * sAsz + (row * APAD + ch * 8) * 2,
                       Ag + (long)row * K + k0 + ch * 8);
        }
#pragma unroll
        for (int i = 0; i < 2; i++) {
            int c   = tid + 256 * i;
            int row = c >> 4, ch = c & 15;
            cp_async16(sB + buf * sBsz + (row * BPAD + ch * 8) * 2,
                       Bg + (long)(k0 + row) * N + bn + ch * 8);
        }
        cp_commit();
    };

    load_tiles(0, 0);

    const int nIter = K / GBK;
    for (int it = 0; it < nIter; it++) {
        int buf = it & 1;
        cp_wait_all();
        __syncthreads();
        if (it + 1 < nIter) load_tiles(buf ^ 1, (it + 1) * GBK);

#pragma unroll
        for (int ks = 0; ks < 2; ks++) {
            uint32_t afrag[4][4];
            uint32_t bfrag[4][2];
            int lrow = lane & 15, lcol = (lane >> 4) * 8;
#pragma unroll
            for (int mi = 0; mi < 4; mi++) {
                uint32_t addr = sA + buf * sAsz +
                    ((64 * wm + 16 * mi + lrow) * APAD + ks * 16 + lcol) * 2;
                ldsm_x4(afrag[mi][0], afrag[mi][1], afrag[mi][2], afrag[mi][3], addr);
            }
#pragma unroll
            for (int nj2 = 0; nj2 < 2; nj2++) {
                uint32_t addr = sB + buf * sBsz +
                    ((ks * 16 + lrow) * BPAD + 32 * wn + 16 * nj2 + lcol) * 2;
                uint32_t r0, r1, r2, r3;
                ldsm_x4_t(r0, r1, r2, r3, addr);
                bfrag[2 * nj2][0] = r0;     bfrag[2 * nj2][1] = r1;
                bfrag[2 * nj2 + 1][0] = r2; bfrag[2 * nj2 + 1][1] = r3;
            }
#pragma unroll
            for (int mi = 0; mi < 4; mi++)
#pragma unroll
                for (int nj = 0; nj < 4; nj++)
                    mma16816(acc[mi][nj], afrag[mi], bfrag[nj]);
        }
        __syncthreads();
    }

    float* Cb = C + (long)blockIdx.z * strideC;
    const float* Ad = addend ? (addend + (long)blockIdx.z * strideAdd) : nullptr;
    int g = lane >> 2, tg = lane & 3;
#pragma unroll
    for (int mi = 0; mi < 4; mi++) {
        int row0 = bm + 64 * wm + 16 * mi + g;
        int row1 = row0 + 8;
        float bv0 = bias ? bias[row0] : 0.f;
        float bv1 = bias ? bias[row1] : 0.f;
#pragma unroll
        for (int nj = 0; nj < 4; nj++) {
            int col = bn + 32 * wn + 8 * nj + 2 * tg;
            float v00 = acc[mi][nj][0] + bv0;
            float v01 = acc[mi][nj][1] + bv0;
            float v10 = acc[mi][nj][2] + bv1;
            float v11 = acc[mi][nj][3] + bv1;
            if (Ad) {
                v00 += Ad[(long)row0 * N + col];
                v01 += Ad[(long)row0 * N + col + 1];
                v10 += Ad[(long)row1 * N + col];
                v11 += Ad[(long)row1 * N + col + 1];
            }
            if (relu) {
                v00 = fmaxf(v00, 0.f); v01 = fmaxf(v01, 0.f);
                v10 = fmaxf(v10, 0.f); v11 = fmaxf(v11, 0.f);
            }
            Cb[(long)row0 * N + col]     = v00;
            Cb[(long)row0 * N + col + 1] = v01;
            Cb[(long)row1 * N + col]     = v10;
            Cb[(long)row1 * N + col + 1] = v11;
        }
    }
}

// ---------------- tiled banded attention -------------------------------------
// Block = (64-query tile, head, batch). Valid keys for query i: j in [i+257, i+512].
// j' = j - (i0+257) in [0, 319); for query qi valid j' in [qi, qi+255].
// BD[i][j] = qr(i) . rk[:, 768 + (j'-qi)]  -> precomputed table BDs[qi][t], t = j'-qi.
// Softmax without max-subtraction (scores are O(10); exp safe in fp32).
#define AT_SMEM ((64*65*2 + 64*258 + 64*260 + 4*64 + 64) * 4)

__global__ __launch_bounds__(256)
void attn_tiled_kernel(const float* __restrict__ wheads,
                       const float* __restrict__ rk,
                       const float* __restrict__ rwb,
                       const float* __restrict__ rrb,
                       float*       __restrict__ avec)
{
    extern __shared__ float sm[];
    float* qw   = sm;                       // [qi][d]  stride 65
    float* qr   = qw  + 64 * 65;            // [qi][d]  stride 65
    float* BDs  = qr  + 64 * 65;            // [qi][t]  stride 258 (t in [0,256))
    float* U    = BDs + 64 * 258;           // union region, 64*260 floats
    float* red  = U   + 64 * 260;           // [4][64]
    float* sinv = red + 4 * 64;             // [64]
    float* Rs = U;                          // [d][t]   stride 260 (phase 1)
    float* Ks = U;                          // [jj][d]  stride 65  (phase 2)
    float* Vs = U + 64 * 65;                // [jj][d]  stride 65
    float* Ps = U + 2 * 64 * 65;            // [qi][jj] stride 65

    const int i0 = blockIdx.x * 64;
    const int h  = blockIdx.y;
    const int b  = blockIdx.z;
    const int tid = threadIdx.x;

    const float* W  = wheads + (long)b * (3 * D_MODEL) * KLEN;
    const float* Qg = W + (long)(h * DHEAD) * KLEN;
    const float* Kg = W + (long)(D_MODEL + h * DHEAD) * KLEN;
    const float* Vg = W + (long)(2 * D_MODEL + h * DHEAD) * KLEN;

    // phase 0: load q slab (64 d x 64 qi), add biases
    for (int idx = tid; idx < 64 * 64; idx += 256) {
        int d = idx >> 6, q = idx & 63;
        float qv = Qg[(long)d * KLEN + MLEN + i0 + q];
        qw[q * 65 + d] = qv + rwb[h * DHEAD + d];
        qr[q * 65 + d] = qv + rrb[h * DHEAD + d];
    }
    // load R window rk[:, 768..1023] as Rs[d][t]
    for (int idx = tid; idx < 64 * 256; idx += 256) {
        int d = idx >> 8, t = idx & 255;
        Rs[d * 260 + t] = rk[(long)(h * DHEAD + d) * KLEN + 768 + t];
    }
    __syncthreads();

    // phase 1: BD table. thread (qi = tid&63, tg = tid>>6) covers t in [tg*64, tg*64+64)
    {
        int q = tid & 63, tg = tid >> 6;
        for (int tt = 0; tt < 64; tt++) {
            int t = tg * 64 + tt;
            float acc = 0.f;
#pragma unroll 16
            for (int d = 0; d < 64; d++)
                acc += qr[q * 65 + d] * Rs[d * 260 + t];
            BDs[q * 258 + t] = acc;
        }
    }

    // phase 2: chunked band attention
    const int qi = tid & 63;
    const int jg = tid >> 6;
    float O[16];
#pragma unroll
    for (int u = 0; u < 16; u++) O[u] = 0.f;
    float sume = 0.f;

    for (int c = 0; c < 5; c++) {
        int jb = c * 64;
        __syncthreads();   // prev chunk's Ps/Vs reads (and Rs reads) complete
        // load K/V chunk: Ks/Vs[jj][d]
        for (int idx = tid; idx < 64 * 64; idx += 256) {
            int d = idx >> 6, jj = idx & 63;
            int jglob = i0 + 257 + jb + jj;
            float kv = 0.f, vv = 0.f;
            if (jglob < KLEN) {
                kv = Kg[(long)d * KLEN + jglob];
                vv = Vg[(long)d * KLEN + jglob];
            }
            Ks[jj * 65 + d] = kv;
            Vs[jj * 65 + d] = vv;
        }
        __syncthreads();

        // scores: thread (qi, jg) computes jj in [jg*16, jg*16+16)
        {
            float acc[16];
#pragma unroll
            for (int u = 0; u < 16; u++) acc[u] = 0.f;
#pragma unroll 8
            for (int d = 0; d < 64; d++) {
                float qv = qw[qi * 65 + d];
#pragma unroll
                for (int u = 0; u < 16; u++)
                    acc[u] += qv * Ks[(jg * 16 + u) * 65 + d];
            }
#pragma unroll
            for (int u = 0; u < 16; u++) {
                int jp = jb + jg * 16 + u;
                int t  = jp - qi;
                float pv = 0.f;
                if (t >= 0 && t < 256)
                    pv = __expf((acc[u] + BDs[qi * 258 + t]) * 0.125f);
                sume += pv;
                Ps[qi * 65 + jg * 16 + u] = pv;
            }
        }
        __syncthreads();

        // AV: thread (qi, jg) accumulates d in [jg*16, jg*16+16)
#pragma unroll 4
        for (int jj = 0; jj < 64; jj++) {
            float pv = Ps[qi * 65 + jj];
#pragma unroll
            for (int u = 0; u < 16; u++)
                O[u] += pv * Vs[jj * 65 + jg * 16 + u];
        }
    }

    // normalize + write
    red[jg * 64 + qi] = sume;
    __syncthreads();
    if (tid < 64)
        sinv[tid] = 1.f / (red[tid] + red[64 + tid] + red[128 + tid] + red[192 + tid]);
    __syncthreads();
    float inv = sinv[qi];
    float* outp = avec + (long)b * D_MODEL * QLEN + (long)(h * DHEAD) * QLEN + i0;
#pragma unroll
    for (int u = 0; u < 16; u++)
        outp[(long)(jg * 16 + u) * QLEN + qi] = O[u] * inv;
}

// ---------------- channel LayerNorm ------------------------------------------
__global__ __launch_bounds__(256)
void ln_kernel(const float* __restrict__ y, float* __restrict__ out)
{
    int b  = blockIdx.y;
    int t0 = blockIdx.x * 32;
    int tid = threadIdx.x;
    int tt = tid & 31, cg = tid >> 5;
    const float* Y = y + (long)b * D_MODEL * QLEN;

    float s = 0.f, s2 = 0.f;
    for (int c = cg * 128; c < cg * 128 + 128; c++) {
        float v = Y[(long)c * QLEN + t0 + tt];
        s += v; s2 += v * v;
    }
    __shared__ float ssum[8][32], ssq[8][32];
    __shared__ float smean[32], srstd[32];
    ssum[cg][tt] = s; ssq[cg][tt] = s2;
    __syncthreads();
    if (tid < 32) {
        float ts = 0.f, ts2 = 0.f;
#pragma unroll
        for (int g = 0; g < 8; g++) { ts += ssum[g][tid]; ts2 += ssq[g][tid]; }
        float mean = ts * (1.0f / D_MODEL);
        float var  = ts2 * (1.0f / D_MODEL) - mean * mean;
        smean[tid] = mean;
        srstd[tid] = rsqrtf(var + 1e-5f);
    }
    __syncthreads();
    float mean = smean[tt], rstd = srstd[tt];
    float* O = out + (long)b * D_MODEL * QLEN;
    for (int c = cg * 128; c < cg * 128 + 128; c++) {
        float v = Y[(long)c * QLEN + t0 + tt];
        O[(long)c * QLEN + t0 + tt] = (v - mean) * rstd;
    }
}

// ---------------- launcher ---------------------------------------------------
extern "C" void kernel_launch(void* const* d_in, const int* in_sizes, int n_in,
                              void* d_out, int out_size)
{
    const float* z1ss    = (const float*)d_in[0];
    const float* uss     = (const float*)d_in[1];
    const float* z0      = (const float*)d_in[2];
    const float* pos_emb = (const float*)d_in[3];
    const float* qkv_w   = (const float*)d_in[4];
    const float* r_w     = (const float*)d_in[5];
    const float* r_w_bias= (const float*)d_in[6];
    const float* r_r_bias= (const float*)d_in[7];
    const float* o_w     = (const float*)d_in[8];
    const float* o_b     = (const float*)d_in[9];
    const float* ff1_w   = (const float*)d_in[10];
    const float* ff1_b   = (const float*)d_in[11];
    const float* ff2_w   = (const float*)d_in[12];
    const float* ff2_b   = (const float*)d_in[13];
    float* out = (float*)d_out;

    float *wheads, *rk, *avec, *tmp1, *x, *h, *tmp2;
    bf16 *qkvw3, *rw3, *ow3, *ff1w3, *ff2w3, *pos3, *cat3, *avec3, *x3, *h3;
    cudaGetSymbolAddress((void**)&wheads, g_wheads);
    cudaGetSymbolAddress((void**)&rk,     g_rk);
    cudaGetSymbolAddress((void**)&avec,   g_attnvec);
    cudaGetSymbolAddress((void**)&tmp1,   g_tmp1);
    cudaGetSymbolAddress((void**)&x,      g_x);
    cudaGetSymbolAddress((void**)&h,      g_h);
    cudaGetSymbolAddress((void**)&tmp2,   g_tmp2);
    cudaGetSymbolAddress((void**)&qkvw3,  g_qkvw3);
    cudaGetSymbolAddress((void**)&rw3,    g_rw3);
    cudaGetSymbolAddress((void**)&ow3,    g_ow3);
    cudaGetSymbolAddress((void**)&ff1w3,  g_ff1w3);
    cudaGetSymbolAddress((void**)&ff2w3,  g_ff2w3);
    cudaGetSymbolAddress((void**)&pos3,   g_pos3);
    cudaGetSymbolAddress((void**)&cat3,   g_cat3);
    cudaGetSymbolAddress((void**)&avec3,  g_avec3);
    cudaGetSymbolAddress((void**)&x3,     g_x3);
    cudaGetSymbolAddress((void**)&h3,     g_h3);

    cudaFuncSetAttribute(attn_tiled_kernel,
                         cudaFuncAttributeMaxDynamicSharedMemorySize, AT_SMEM);

    // ---- operand expansions ----
    expandA_kernel<<<dim3(D_MODEL / 256, 3 * D_MODEL), 256>>>(qkv_w, qkvw3, D_MODEL);
    expandA_kernel<<<dim3(D_MODEL / 256, D_MODEL),     256>>>(r_w,   rw3,   D_MODEL);
    expandA_kernel<<<dim3(D_MODEL / 256, D_MODEL),     256>>>(o_w,   ow3,   D_MODEL);
    expandA_kernel<<<dim3(D_MODEL / 256, DINNER),      256>>>(ff1_w, ff1w3, D_MODEL);
    expandA_kernel<<<dim3(DINNER / 256,  D_MODEL),     256>>>(ff2_w, ff2w3, DINNER);
    expandB_kernel<<<dim3(KLEN / 256, D_MODEL, 1), 256>>>(pos_emb, pos3, KLEN, 0, 0);
    expand_cat_kernel<<<dim3(KLEN / 256, D_MODEL, BSZ), 256>>>(z0, z1ss);

    // ---- QKV ----
    gemm_bf16_kernel<<<dim3(KLEN / GBN, 3 * D_MODEL / GBM, BSZ), 256>>>(
        qkvw3, cat3, wheads, nullptr, uss,
        3 * D_MODEL, KLEN, 3 * D_MODEL,
        (long)3 * D_MODEL * KLEN, (long)3 * D_MODEL * KLEN, (long)3 * D_MODEL * KLEN, 0);

    // ---- r_head_k ----
    gemm_bf16_kernel<<<dim3(KLEN / GBN, D_MODEL / GBM, 1), 256>>>(
        rw3, pos3, rk, nullptr, nullptr,
        D_MODEL, KLEN, 3 * D_MODEL, 0, 0, 0, 0);

    // ---- tiled banded attention ----
    attn_tiled_kernel<<<dim3(QLEN / 64, NHEAD, BSZ), 256, AT_SMEM>>>(
        wheads, rk, r_w_bias, r_r_bias, avec);

    // ---- O-proj ----
    expandB_kernel<<<dim3(QLEN / 256, D_MODEL, BSZ), 256>>>(
        avec, avec3, QLEN, (long)D_MODEL * QLEN, (long)3 * D_MODEL * QLEN);
    gemm_bf16_kernel<<<dim3(QLEN / GBN, D_MODEL / GBM, BSZ), 256>>>(
        ow3, avec3, tmp1, o_b, z1ss,
        D_MODEL, QLEN, 3 * D_MODEL,
        (long)3 * D_MODEL * QLEN, (long)D_MODEL * QLEN, (long)D_MODEL * QLEN, 0);

    // ---- x = LN(tmp1) ----
    ln_kernel<<<dim3(QLEN / 32, BSZ), 256>>>(tmp1, x);

    // ---- FF1 ----
    expandB_kernel<<<dim3(QLEN / 256, D_MODEL, BSZ), 256>>>(
        x, x3, QLEN, (long)D_MODEL * QLEN, (long)3 * D_MODEL * QLEN);
    gemm_bf16_kernel<<<dim3(QLEN / GBN, DINNER / GBM, BSZ), 256>>>(
        ff1w3, x3, h, ff1_b, nullptr,
        DINNER, QLEN, 3 * D_MODEL,
        (long)3 * D_MODEL * QLEN, (long)DINNER * QLEN, 0, 1);

    // ---- FF2 ----
    expandB_kernel<<<dim3(QLEN / 256, DINNER, BSZ), 256>>>(
        h, h3, QLEN, (long)DINNER * QLEN, (long)3 * DINNER * QLEN);
    gemm_bf16_kernel<<<dim3(QLEN / GBN, D_MODEL / GBM, BSZ), 256>>>(
        ff2w3, h3, tmp2, ff2_b, x,
        D_MODEL, QLEN, 3 * DINNER,
        (long)3 * DINNER * QLEN, (long)D_MODEL * QLEN, (long)D_MODEL * QLEN, 0);

    // ---- out = LN(tmp2) ----
    ln_kernel<<<dim3(QLEN / 32, BSZ), 256>>>(tmp2, out);
}

// round 6
// speedup vs baseline: 3.0257x; 1.0205x over previous
#include <cuda_runtime.h>
#include <cuda_bf16.h>
#include <cstdint>

#define BSZ     4
#define D_MODEL 1024
#define QLEN    512
#define MLEN    512
#define KLEN    1024
#define NHEAD   16
#define DHEAD   64
#define DINNER  4096

typedef __nv_bfloat16 bf16;

// ---------------- fp32 scratch ----------------------------------------------
__device__ float g_wheads[BSZ * 3 * D_MODEL * KLEN];       // 48 MB
__device__ float g_rk[D_MODEL * KLEN];                     // 4 MB
__device__ float g_attnvec[BSZ * D_MODEL * QLEN];          // 8 MB
__device__ float g_tmp1[BSZ * D_MODEL * QLEN];             // 8 MB
__device__ float g_x[BSZ * D_MODEL * QLEN];                // 8 MB
__device__ float g_h[BSZ * DINNER * QLEN];                 // 32 MB
__device__ float g_tmp2[BSZ * D_MODEL * QLEN];             // 8 MB

// ---------------- bf16-split (hi,hi,lo / hi,lo,hi) scratch -------------------
__device__ bf16 g_qkvw3[3 * D_MODEL * 3 * D_MODEL];
__device__ bf16 g_rw3  [D_MODEL * 3 * D_MODEL];
__device__ bf16 g_ow3  [D_MODEL * 3 * D_MODEL];
__device__ bf16 g_ff1w3[DINNER * 3 * D_MODEL];
__device__ bf16 g_ff2w3[D_MODEL * 3 * DINNER];
__device__ bf16 g_pos3 [3 * D_MODEL * KLEN];
__device__ bf16 g_cat3 [BSZ * 3 * D_MODEL * KLEN];
__device__ bf16 g_avec3[BSZ * 3 * D_MODEL * QLEN];
__device__ bf16 g_x3   [BSZ * 3 * D_MODEL * QLEN];
__device__ bf16 g_h3   [BSZ * 3 * DINNER * QLEN];

// ---------------- helpers ----------------------------------------------------
__device__ __forceinline__ void split_bf16(float x, bf16& hi, bf16& lo)
{
    hi = __float2bfloat16(x);
    lo = __float2bfloat16(x - __bfloat162float(hi));
}

__device__ __forceinline__ void cp_async16(uint32_t smem_dst, const void* gmem_src)
{
    asm volatile("cp.async.cg.shared.global [%0], [%1], 16;\n"
                 :: "r"(smem_dst), "l"(gmem_src));
}
__device__ __forceinline__ void cp_commit()
{
    asm volatile("cp.async.commit_group;\n");
}
__device__ __forceinline__ void cp_wait_all()
{
    asm volatile("cp.async.wait_group 0;\n");
}
__device__ __forceinline__ void ldsm_x4(uint32_t& r0, uint32_t& r1, uint32_t& r2, uint32_t& r3, uint32_t addr)
{
    asm volatile("ldmatrix.sync.aligned.m8n8.x4.shared.b16 {%0,%1,%2,%3}, [%4];\n"
                 : "=r"(r0), "=r"(r1), "=r"(r2), "=r"(r3) : "r"(addr));
}
__device__ __forceinline__ void ldsm_x4_t(uint32_t& r0, uint32_t& r1, uint32_t& r2, uint32_t& r3, uint32_t addr)
{
    asm volatile("ldmatrix.sync.aligned.m8n8.x4.trans.shared.b16 {%0,%1,%2,%3}, [%4];\n"
                 : "=r"(r0), "=r"(r1), "=r"(r2), "=r"(r3) : "r"(addr));
}
__device__ __forceinline__ void mma16816(float* c, const uint32_t* a, const uint32_t* b)
{
    asm volatile(
        "mma.sync.aligned.m16n8k16.row.col.f32.bf16.bf16.f32 "
        "{%0,%1,%2,%3}, {%4,%5,%6,%7}, {%8,%9}, {%0,%1,%2,%3};\n"
        : "+f"(c[0]), "+f"(c[1]), "+f"(c[2]), "+f"(c[3])
        : "r"(a[0]), "r"(a[1]), "r"(a[2]), "r"(a[3]), "r"(b[0]), "r"(b[1]));
}

// ---------------- expansion kernels ------------------------------------------
__global__ void expandA_kernel(const float* __restrict__ in, bf16* __restrict__ out, int K)
{
    int k = blockIdx.x * 256 + threadIdx.x;
    int m = blockIdx.y;
    float x = in[(long)m * K + k];
    bf16 hi, lo; split_bf16(x, hi, lo);
    bf16* o = out + (long)m * 3 * K + 3 * k;
    o[0] = hi; o[1] = hi; o[2] = lo;
}

__global__ void expandB_kernel(const float* __restrict__ in, bf16* __restrict__ out,
                               int N, long sIn, long sOut)
{
    int n = blockIdx.x * 256 + threadIdx.x;
    int k = blockIdx.y;
    float x = in[(long)blockIdx.z * sIn + (long)k * N + n];
    bf16 hi, lo; split_bf16(x, hi, lo);
    bf16* o = out + (long)blockIdx.z * sOut + (long)(3 * k) * N + n;
    o[0] = hi; o[N] = lo; o[2 * N] = hi;
}

__global__ void expand_cat_kernel(const float* __restrict__ z0, const float* __restrict__ z1ss)
{
    int t = blockIdx.x * 256 + threadIdx.x;
    int d = blockIdx.y;
    int b = blockIdx.z;
    float x = (t < MLEN) ? z0[((long)b * D_MODEL + d) * MLEN + t]
                         : z1ss[((long)b * D_MODEL + d) * QLEN + (t - MLEN)];
    bf16 hi, lo; split_bf16(x, hi, lo);
    bf16* o = g_cat3 + (long)b * 3 * D_MODEL * KLEN + (long)(3 * d) * KLEN + t;
    o[0] = hi; o[KLEN] = lo; o[2 * KLEN] = hi;
}

// ---------------- tensor-core GEMM (mma.sync, known-good) --------------------
#define GBM 128
#define GBN 128
#define GBK 32
#define APAD 40
#define BPAD 136

__global__ __launch_bounds__(256)
void gemm_bf16_kernel(const bf16* __restrict__ A,
                      const bf16* __restrict__ B,
                      float*      __restrict__ C,
                      const float* __restrict__ bias,
                      const float* __restrict__ addend,
                      int M, int N, int K,
                      long strideB, long strideC, long strideAdd,
                      int relu)
{
    __shared__ bf16 As[2][GBM * APAD];
    __shared__ bf16 Bs[2][GBK * BPAD];

    const int tid  = threadIdx.x;
    const int lane = tid & 31;
    const int warp = tid >> 5;
    const int wm = warp >> 2;
    const int wn = warp & 3;
    const int bn = blockIdx.x * GBN;
    const int bm = blockIdx.y * GBM;

    const bf16* Ag = A + (long)bm * K;
    const bf16* Bg = B + (long)blockIdx.z * strideB;

    uint32_t sA = (uint32_t)__cvta_generic_to_shared(&As[0][0]);
    uint32_t sB = (uint32_t)__cvta_generic_to_shared(&Bs[0][0]);
    const uint32_t sAsz = GBM * APAD * 2;
    const uint32_t sBsz = GBK * BPAD * 2;

    float acc[4][4][4];
#pragma unroll
    for (int i = 0; i < 4; i++)
#pragma unroll
        for (int j = 0; j < 4; j++)
#pragma unroll
            for (int r = 0; r < 4; r++) acc[i][j][r] = 0.f;

    auto load_tiles = [&](int buf, int k0) {
#pragma unroll
        for (int i = 0; i < 2; i++) {
            int c   = tid + 256 * i;
            int row = c >> 2, ch = c & 3;
            cp_async16(sA + buf * sAsz + (row * APAD + ch * 8) * 2,
                       Ag + (long)row * K + k0 + ch * 8);
        }
#pragma unroll
        for (int i = 0; i < 2; i++) {
            int c   = tid + 256 * i;
            int row = c >> 4, ch = c & 15;
            cp_async16(sB + buf * sBsz + (row * BPAD + ch * 8) * 2,
                       Bg + (long)(k0 + row) * N + bn + ch * 8);
        }
        cp_commit();
    };

    load_tiles(0, 0);

    const int nIter = K / GBK;
    for (int it = 0; it < nIter; it++) {
        int buf = it & 1;
        cp_wait_all();
        __syncthreads();
        if (it + 1 < nIter) load_tiles(buf ^ 1, (it + 1) * GBK);

#pragma unroll
        for (int ks = 0; ks < 2; ks++) {
            uint32_t afrag[4][4];
            uint32_t bfrag[4][2];
            int lrow = lane & 15, lcol = (lane >> 4) * 8;
#pragma unroll
            for (int mi = 0; mi < 4; mi++) {
                uint32_t addr = sA + buf * sAsz +
                    ((64 * wm + 16 * mi + lrow) * APAD + ks * 16 + lcol) * 2;
                ldsm_x4(afrag[mi][0], afrag[mi][1], afrag[mi][2], afrag[mi][3], addr);
            }
#pragma unroll
            for (int nj2 = 0; nj2 < 2; nj2++) {
                uint32_t addr = sB + buf * sBsz +
                    ((ks * 16 + lrow) * BPAD + 32 * wn + 16 * nj2 + lcol) * 2;
                uint32_t r0, r1, r2, r3;
                ldsm_x4_t(r0, r1, r2, r3, addr);
                bfrag[2 * nj2][0] = r0;     bfrag[2 * nj2][1] = r1;
                bfrag[2 * nj2 + 1][0] = r2; bfrag[2 * nj2 + 1][1] = r3;
            }
#pragma unroll
            for (int mi = 0; mi < 4; mi++)
#pragma unroll
                for (int nj = 0; nj < 4; nj++)
                    mma16816(acc[mi][nj], afrag[mi], bfrag[nj]);
        }
        __syncthreads();
    }

    float* Cb = C + (long)blockIdx.z * strideC;
    const float* Ad = addend ? (addend + (long)blockIdx.z * strideAdd) : nullptr;
    int g = lane >> 2, tg = lane & 3;
#pragma unroll
    for (int mi = 0; mi < 4; mi++) {
        int row0 = bm + 64 * wm + 16 * mi + g;
        int row1 = row0 + 8;
        float bv0 = bias ? bias[row0] : 0.f;
        float bv1 = bias ? bias[row1] : 0.f;
#pragma unroll
        for (int nj = 0; nj < 4; nj++) {
            int col = bn + 32 * wn + 8 * nj + 2 * tg;
            float v00 = acc[mi][nj][0] + bv0;
            float v01 = acc[mi][nj][1] + bv0;
            float v10 = acc[mi][nj][2] + bv1;
            float v11 = acc[mi][nj][3] + bv1;
            if (Ad) {
                v00 += Ad[(long)row0 * N + col];
                v01 += Ad[(long)row0 * N + col + 1];
                v10 += Ad[(long)row1 * N + col];
                v11 += Ad[(long)row1 * N + col + 1];
            }
            if (relu) {
                v00 = fmaxf(v00, 0.f); v01 = fmaxf(v01, 0.f);
                v10 = fmaxf(v10, 0.f); v11 = fmaxf(v11, 0.f);
            }
            Cb[(long)row0 * N + col]     = v00;
            Cb[(long)row0 * N + col + 1] = v01;
            Cb[(long)row1 * N + col]     = v10;
            Cb[(long)row1 * N + col + 1] = v11;
        }
    }
}

// ---------------- tiled banded attention -------------------------------------
// Block = (64-query tile, head, batch). Valid keys for query i: j in [i+257, i+512].
// j' = j - (i0+257) in [0, 319); for query qi valid j' in [qi, qi+255].
// BD[i][j] = qr(i) . rk[:, 768 + (j'-qi)]  -> precomputed table BDs[qi][t], t = j'-qi.
// Softmax without max-subtraction (scores are O(10); exp safe in fp32).
#define AT_SMEM ((64*65*2 + 64*258 + 64*260 + 4*64 + 64) * 4)

__global__ __launch_bounds__(256)
void attn_tiled_kernel(const float* __restrict__ wheads,
                       const float* __restrict__ rk,
                       const float* __restrict__ rwb,
                       const float* __restrict__ rrb,
                       float*       __restrict__ avec)
{
    extern __shared__ float sm[];
    float* qw   = sm;                       // [qi][d]  stride 65
    float* qr   = qw  + 64 * 65;            // [qi][d]  stride 65
    float* BDs  = qr  + 64 * 65;            // [qi][t]  stride 258 (t in [0,256))
    float* U    = BDs + 64 * 258;           // union region, 64*260 floats
    float* red  = U   + 64 * 260;           // [4][64]
    float* sinv = red + 4 * 64;             // [64]
    float* Rs = U;                          // [d][t]   stride 260 (phase 1)
    float* Ks = U;                          // [jj][d]  stride 65  (phase 2)
    float* Vs = U + 64 * 65;                // [jj][d]  stride 65
    float* Ps = U + 2 * 64 * 65;            // [qi][jj] stride 65

    const int i0 = blockIdx.x * 64;
    const int h  = blockIdx.y;
    const int b  = blockIdx.z;
    const int tid = threadIdx.x;

    const float* W  = wheads + (long)b * (3 * D_MODEL) * KLEN;
    const float* Qg = W + (long)(h * DHEAD) * KLEN;
    const float* Kg = W + (long)(D_MODEL + h * DHEAD) * KLEN;
    const float* Vg = W + (long)(2 * D_MODEL + h * DHEAD) * KLEN;

    // phase 0: load q slab (64 d x 64 qi), add biases
    for (int idx = tid; idx < 64 * 64; idx += 256) {
        int d = idx >> 6, q = idx & 63;
        float qv = Qg[(long)d * KLEN + MLEN + i0 + q];
        qw[q * 65 + d] = qv + rwb[h * DHEAD + d];
        qr[q * 65 + d] = qv + rrb[h * DHEAD + d];
    }
    // load R window rk[:, 768..1023] as Rs[d][t]
    for (int idx = tid; idx < 64 * 256; idx += 256) {
        int d = idx >> 8, t = idx & 255;
        Rs[d * 260 + t] = rk[(long)(h * DHEAD + d) * KLEN + 768 + t];
    }
    __syncthreads();

    // phase 1: BD table. thread (qi = tid&63, tg = tid>>6) covers t in [tg*64, tg*64+64)
    {
        int q = tid & 63, tg = tid >> 6;
        for (int tt = 0; tt < 64; tt++) {
            int t = tg * 64 + tt;
            float acc = 0.f;
#pragma unroll 16
            for (int d = 0; d < 64; d++)
                acc += qr[q * 65 + d] * Rs[d * 260 + t];
            BDs[q * 258 + t] = acc;
        }
    }

    // phase 2: chunked band attention
    const int qi = tid & 63;
    const int jg = tid >> 6;
    float O[16];
#pragma unroll
    for (int u = 0; u < 16; u++) O[u] = 0.f;
    float sume = 0.f;

    for (int c = 0; c < 5; c++) {
        int jb = c * 64;
        __syncthreads();   // prev chunk's Ps/Vs reads (and Rs reads) complete
        // load K/V chunk: Ks/Vs[jj][d]
        for (int idx = tid; idx < 64 * 64; idx += 256) {
            int d = idx >> 6, jj = idx & 63;
            int jglob = i0 + 257 + jb + jj;
            float kv = 0.f, vv = 0.f;
            if (jglob < KLEN) {
                kv = Kg[(long)d * KLEN + jglob];
                vv = Vg[(long)d * KLEN + jglob];
            }
            Ks[jj * 65 + d] = kv;
            Vs[jj * 65 + d] = vv;
        }
        __syncthreads();

        // scores: thread (qi, jg) computes jj in [jg*16, jg*16+16)
        {
            float acc[16];
#pragma unroll
            for (int u = 0; u < 16; u++) acc[u] = 0.f;
#pragma unroll 8
            for (int d = 0; d < 64; d++) {
                float qv = qw[qi * 65 + d];
#pragma unroll
                for (int u = 0; u < 16; u++)
                    acc[u] += qv * Ks[(jg * 16 + u) * 65 + d];
            }
#pragma unroll
            for (int u = 0; u < 16; u++) {
                int jp = jb + jg * 16 + u;
                int t  = jp - qi;
                float pv = 0.f;
                if (t >= 0 && t < 256)
                    pv = __expf((acc[u] + BDs[qi * 258 + t]) * 0.125f);
                sume += pv;
                Ps[qi * 65 + jg * 16 + u] = pv;
            }
        }
        __syncthreads();

        // AV: thread (qi, jg) accumulates d in [jg*16, jg*16+16)
#pragma unroll 4
        for (int jj = 0; jj < 64; jj++) {
            float pv = Ps[qi * 65 + jj];
#pragma unroll
            for (int u = 0; u < 16; u++)
                O[u] += pv * Vs[jj * 65 + jg * 16 + u];
        }
    }

    // normalize + write
    red[jg * 64 + qi] = sume;
    __syncthreads();
    if (tid < 64)
        sinv[tid] = 1.f / (red[tid] + red[64 + tid] + red[128 + tid] + red[192 + tid]);
    __syncthreads();
    float inv = sinv[qi];
    float* outp = avec + (long)b * D_MODEL * QLEN + (long)(h * DHEAD) * QLEN + i0;
#pragma unroll
    for (int u = 0; u < 16; u++)
        outp[(long)(jg * 16 + u) * QLEN + qi] = O[u] * inv;
}

// ---------------- channel LayerNorm ------------------------------------------
__global__ __launch_bounds__(256)
void ln_kernel(const float* __restrict__ y, float* __restrict__ out)
{
    int b  = blockIdx.y;
    int t0 = blockIdx.x * 32;
    int tid = threadIdx.x;
    int tt = tid & 31, cg = tid >> 5;
    const float* Y = y + (long)b * D_MODEL * QLEN;

    float s = 0.f, s2 = 0.f;
    for (int c = cg * 128; c < cg * 128 + 128; c++) {
        float v = Y[(long)c * QLEN + t0 + tt];
        s += v; s2 += v * v;
    }
    __shared__ float ssum[8][32], ssq[8][32];
    __shared__ float smean[32], srstd[32];
    ssum[cg][tt] = s; ssq[cg][tt] = s2;
    __syncthreads();
    if (tid < 32) {
        float ts = 0.f, ts2 = 0.f;
#pragma unroll
        for (int g = 0; g < 8; g++) { ts += ssum[g][tid]; ts2 += ssq[g][tid]; }
        float mean = ts * (1.0f / D_MODEL);
        float var  = ts2 * (1.0f / D_MODEL) - mean * mean;
        smean[tid] = mean;
        srstd[tid] = rsqrtf(var + 1e-5f);
    }
    __syncthreads();
    float mean = smean[tt], rstd = srstd[tt];
    float* O = out + (long)b * D_MODEL * QLEN;
    for (int c = cg * 128; c < cg * 128 + 128; c++) {
        float v = Y[(long)c * QLEN + t0 + tt];
        O[(long)c * QLEN + t0 + tt] = (v - mean) * rstd;
    }
}

// ---------------- launcher ---------------------------------------------------
extern "C" void kernel_launch(void* const* d_in, const int* in_sizes, int n_in,
                              void* d_out, int out_size)
{
    const float* z1ss    = (const float*)d_in[0];
    const float* uss     = (const float*)d_in[1];
    const float* z0      = (const float*)d_in[2];
    const float* pos_emb = (const float*)d_in[3];
    const float* qkv_w   = (const float*)d_in[4];
    const float* r_w     = (const float*)d_in[5];
    const float* r_w_bias= (const float*)d_in[6];
    const float* r_r_bias= (const float*)d_in[7];
    const float* o_w     = (const float*)d_in[8];
    const float* o_b     = (const float*)d_in[9];
    const float* ff1_w   = (const float*)d_in[10];
    const float* ff1_b   = (const float*)d_in[11];
    const float* ff2_w   = (const float*)d_in[12];
    const float* ff2_b   = (const float*)d_in[13];
    float* out = (float*)d_out;

    float *wheads, *rk, *avec, *tmp1, *x, *h, *tmp2;
    bf16 *qkvw3, *rw3, *ow3, *ff1w3, *ff2w3, *pos3, *cat3, *avec3, *x3, *h3;
    cudaGetSymbolAddress((void**)&wheads, g_wheads);
    cudaGetSymbolAddress((void**)&rk,     g_rk);
    cudaGetSymbolAddress((void**)&avec,   g_attnvec);
    cudaGetSymbolAddress((void**)&tmp1,   g_tmp1);
    cudaGetSymbolAddress((void**)&x,      g_x);
    cudaGetSymbolAddress((void**)&h,      g_h);
    cudaGetSymbolAddress((void**)&tmp2,   g_tmp2);
    cudaGetSymbolAddress((void**)&qkvw3,  g_qkvw3);
    cudaGetSymbolAddress((void**)&rw3,    g_rw3);
    cudaGetSymbolAddress((void**)&ow3,    g_ow3);
    cudaGetSymbolAddress((void**)&ff1w3,  g_ff1w3);
    cudaGetSymbolAddress((void**)&ff2w3,  g_ff2w3);
    cudaGetSymbolAddress((void**)&pos3,   g_pos3);
    cudaGetSymbolAddress((void**)&cat3,   g_cat3);
    cudaGetSymbolAddress((void**)&avec3,  g_avec3);
    cudaGetSymbolAddress((void**)&x3,     g_x3);
    cudaGetSymbolAddress((void**)&h3,     g_h3);

    cudaFuncSetAttribute(attn_tiled_kernel,
                         cudaFuncAttributeMaxDynamicSharedMemorySize, AT_SMEM);

    // ---- operand expansions ----
    expandA_kernel<<<dim3(D_MODEL / 256, 3 * D_MODEL), 256>>>(qkv_w, qkvw3, D_MODEL);
    expandA_kernel<<<dim3(D_MODEL / 256, D_MODEL),     256>>>(r_w,   rw3,   D_MODEL);
    expandA_kernel<<<dim3(D_MODEL / 256, D_MODEL),     256>>>(o_w,   ow3,   D_MODEL);
    expandA_kernel<<<dim3(D_MODEL / 256, DINNER),      256>>>(ff1_w, ff1w3, D_MODEL);
    expandA_kernel<<<dim3(DINNER / 256,  D_MODEL),     256>>>(ff2_w, ff2w3, DINNER);
    expandB_kernel<<<dim3(KLEN / 256, D_MODEL, 1), 256>>>(pos_emb, pos3, KLEN, 0, 0);
    expand_cat_kernel<<<dim3(KLEN / 256, D_MODEL, BSZ), 256>>>(z0, z1ss);

    // ---- QKV ----
    gemm_bf16_kernel<<<dim3(KLEN / GBN, 3 * D_MODEL / GBM, BSZ), 256>>>(
        qkvw3, cat3, wheads, nullptr, uss,
        3 * D_MODEL, KLEN, 3 * D_MODEL,
        (long)3 * D_MODEL * KLEN, (long)3 * D_MODEL * KLEN, (long)3 * D_MODEL * KLEN, 0);

    // ---- r_head_k ----
    gemm_bf16_kernel<<<dim3(KLEN / GBN, D_MODEL / GBM, 1), 256>>>(
        rw3, pos3, rk, nullptr, nullptr,
        D_MODEL, KLEN, 3 * D_MODEL, 0, 0, 0, 0);

    // ---- tiled banded attention ----
    attn_tiled_kernel<<<dim3(QLEN / 64, NHEAD, BSZ), 256, AT_SMEM>>>(
        wheads, rk, r_w_bias, r_r_bias, avec);

    // ---- O-proj ----
    expandB_kernel<<<dim3(QLEN / 256, D_MODEL, BSZ), 256>>>(
        avec, avec3, QLEN, (long)D_MODEL * QLEN, (long)3 * D_MODEL * QLEN);
    gemm_bf16_kernel<<<dim3(QLEN / GBN, D_MODEL / GBM, BSZ), 256>>>(
        ow3, avec3, tmp1, o_b, z1ss,
        D_MODEL, QLEN, 3 * D_MODEL,
        (long)3 * D_MODEL * QLEN, (long)D_MODEL * QLEN, (long)D_MODEL * QLEN, 0);

    // ---- x = LN(tmp1) ----
    ln_kernel<<<dim3(QLEN / 32, BSZ), 256>>>(tmp1, x);

    // ---- FF1 ----
    expandB_kernel<<<dim3(QLEN / 256, D_MODEL, BSZ), 256>>>(
        x, x3, QLEN, (long)D_MODEL * QLEN, (long)3 * D_MODEL * QLEN);
    gemm_bf16_kernel<<<dim3(QLEN / GBN, DINNER / GBM, BSZ), 256>>>(
        ff1w3, x3, h, ff1_b, nullptr,
        DINNER, QLEN, 3 * D_MODEL,
        (long)3 * D_MODEL * QLEN, (long)DINNER * QLEN, 0, 1);

    // ---- FF2 ----
    expandB_kernel<<<dim3(QLEN / 256, DINNER, BSZ), 256>>>(
        h, h3, QLEN, (long)DINNER * QLEN, (long)3 * DINNER * QLEN);
    gemm_bf16_kernel<<<dim3(QLEN / GBN, D_MODEL / GBM, BSZ), 256>>>(
        ff2w3, h3, tmp2, ff2_b, x,
        D_MODEL, QLEN, 3 * DINNER,
        (long)3 * DINNER * QLEN, (long)D_MODEL * QLEN, (long)D_MODEL * QLEN, 0);

    // ---- out = LN(tmp2) ----
    ln_kernel<<<dim3(QLEN / 32, BSZ), 256>>>(tmp2, out);
}